// round 1
// baseline (speedup 1.0000x reference)
#include <cuda_runtime.h>
#include <cstdint>

#define N_NODES  50000
#define N_EDGES  800000
#define N_GRAPHS 512
#define F_IN     128
#define DD       256
#define EPS      1e-5f
#define NEG_SLOPE 0.01f

// ---------------- scratch (device globals; no allocation allowed) ----------
__device__ float g_bufA[N_NODES * DD];   // H1 -> x1 -> x2
__device__ float g_bufB[N_NODES * DD];   // agg1 -> H2
__device__ float g_bufC[N_NODES * DD];   // agg2
__device__ float g_C1[4 * DD];
__device__ float g_bc1[DD];
__device__ float g_C2[4 * DD];
__device__ float g_bc2[DD];
__device__ float g_bnsum[DD];
__device__ float g_bnsq[DD];
__device__ unsigned g_gmax[N_GRAPHS];
__device__ float g_denom[N_GRAPHS];
__device__ float g_gate[N_NODES];
__device__ float g_e[N_NODES];

// ---------------- helpers ---------------------------------------------------
__device__ __forceinline__ float leaky(float v) {
    return v >= 0.f ? v : NEG_SLOPE * v;
}

__device__ __forceinline__ unsigned enc_f(float x) {
    unsigned u = __float_as_uint(x);
    return (u & 0x80000000u) ? ~u : (u | 0x80000000u);
}
__device__ __forceinline__ float dec_f(unsigned u) {
    return (u & 0x80000000u) ? __uint_as_float(u ^ 0x80000000u) : __uint_as_float(~u);
}

__device__ __forceinline__ void red_add_v4(float* p, float a, float b, float c, float d) {
    asm volatile("red.global.add.v4.f32 [%0], {%1, %2, %3, %4};"
                 :: "l"(p), "f"(a), "f"(b), "f"(c), "f"(d) : "memory");
}

// ---------------- zero kernels ---------------------------------------------
__global__ void zero_f(float* p, int n) {
    int i = blockIdx.x * blockDim.x + threadIdx.x;
    int stride = gridDim.x * blockDim.x;
    for (; i < n; i += stride) p[i] = 0.f;
}

__global__ void zero_small() {
    int t = blockIdx.x * blockDim.x + threadIdx.x;
    if (t < DD) { g_bnsum[t] = 0.f; g_bnsq[t] = 0.f; }
    if (t < N_GRAPHS) { g_gmax[t] = 0u; g_denom[t] = 0.f; }
}

__global__ void zero_bn() {
    int t = threadIdx.x;
    if (t < DD) { g_bnsum[t] = 0.f; g_bnsq[t] = 0.f; }
}

// ---------------- combined edge matrices ------------------------------------
// C[k][d] = sum_f lin2_w[f][k] * lin_w[d][f];  bc[d] = sum_f lin2_b[f]*lin_w[d][f] + lin_b[d]
__global__ void combine_kernel(
    const float* __restrict__ l2w1, const float* __restrict__ l2b1,
    const float* __restrict__ lw1,  const float* __restrict__ lb1,
    const float* __restrict__ l2w2, const float* __restrict__ l2b2,
    const float* __restrict__ lw2,  const float* __restrict__ lb2)
{
    int d = threadIdx.x;   // 256 threads
    // layer 1: K = F_IN
    {
        float a0 = 0.f, a1 = 0.f, a2 = 0.f, a3 = 0.f, bb = 0.f;
        for (int f = 0; f < F_IN; f++) {
            float w = lw1[d * F_IN + f];
            float4 l2 = *(const float4*)(l2w1 + f * 4);
            a0 += l2.x * w; a1 += l2.y * w; a2 += l2.z * w; a3 += l2.w * w;
            bb += l2b1[f] * w;
        }
        g_C1[0 * DD + d] = a0; g_C1[1 * DD + d] = a1;
        g_C1[2 * DD + d] = a2; g_C1[3 * DD + d] = a3;
        g_bc1[d] = bb + lb1[d];
    }
    // layer 2: K = DD
    {
        float a0 = 0.f, a1 = 0.f, a2 = 0.f, a3 = 0.f, bb = 0.f;
        for (int f = 0; f < DD; f++) {
            float w = lw2[d * DD + f];
            float4 l2 = *(const float4*)(l2w2 + f * 4);
            a0 += l2.x * w; a1 += l2.y * w; a2 += l2.z * w; a3 += l2.w * w;
            bb += l2b2[f] * w;
        }
        g_C2[0 * DD + d] = a0; g_C2[1 * DD + d] = a1;
        g_C2[2 * DD + d] = a2; g_C2[3 * DD + d] = a3;
        g_bc2[d] = bb + lb2[d];
    }
}

// ---------------- GEMM: out[m][n] = sum_k A[row(m)][k] * W[n][k] ------------
// A row-major [?, K] (optionally gathered via idx), W row-major [256, K].
__global__ void gemm_kernel(const float* __restrict__ A, const int* __restrict__ idx,
                            const float* __restrict__ W, float* __restrict__ out,
                            int M, int K)
{
    __shared__ float As[16][72];
    __shared__ float Ws[16][72];
    int bm = blockIdx.x * 64;
    int bn = blockIdx.y * 64;
    int t = threadIdx.x;               // 256 threads
    int lr = t >> 2;                   // 0..63
    int lk = (t & 3) * 4;              // 0,4,8,12
    int tx = t & 15, ty = t >> 4;

    float acc[4][4];
#pragma unroll
    for (int i = 0; i < 4; i++)
#pragma unroll
        for (int j = 0; j < 4; j++) acc[i][j] = 0.f;

    for (int k0 = 0; k0 < K; k0 += 16) {
        // load A tile (with optional gather)
        int m = bm + lr;
        float4 av = make_float4(0.f, 0.f, 0.f, 0.f);
        if (m < M) {
            int r = idx ? __ldg(idx + m) : m;
            av = __ldg((const float4*)(A + (size_t)r * K + k0 + lk));
        }
        As[lk + 0][lr] = av.x; As[lk + 1][lr] = av.y;
        As[lk + 2][lr] = av.z; As[lk + 3][lr] = av.w;
        // load W tile (n = bn + lr is always < 256)
        float4 wv = __ldg((const float4*)(W + (size_t)(bn + lr) * K + k0 + lk));
        Ws[lk + 0][lr] = wv.x; Ws[lk + 1][lr] = wv.y;
        Ws[lk + 2][lr] = wv.z; Ws[lk + 3][lr] = wv.w;
        __syncthreads();
#pragma unroll
        for (int kk = 0; kk < 16; kk++) {
            float a[4], b[4];
#pragma unroll
            for (int i = 0; i < 4; i++) a[i] = As[kk][ty * 4 + i];
#pragma unroll
            for (int j = 0; j < 4; j++) b[j] = Ws[kk][tx * 4 + j];
#pragma unroll
            for (int i = 0; i < 4; i++)
#pragma unroll
                for (int j = 0; j < 4; j++) acc[i][j] += a[i] * b[j];
        }
        __syncthreads();
    }
#pragma unroll
    for (int i = 0; i < 4; i++) {
        int m = bm + ty * 4 + i;
        if (m < M) {
#pragma unroll
            for (int j = 0; j < 4; j++)
                out[(size_t)m * DD + bn + tx * 4 + j] = acc[i][j];
        }
    }
}

// ---------------- edge scatter: agg[dst] += leaky(H[src] + ea@C + bc) -------
__global__ void scatter_kernel(const float* __restrict__ H,
                               const int* __restrict__ src,
                               const int* __restrict__ dst,
                               const float* __restrict__ ea,
                               const float* __restrict__ C,
                               const float* __restrict__ bc,
                               float* __restrict__ agg)
{
    int lane = threadIdx.x & 31;
    int warp = (blockIdx.x * blockDim.x + threadIdx.x) >> 5;
    int nwarps = (gridDim.x * blockDim.x) >> 5;
    int d0 = lane * 8;

    // per-lane constants (each lane owns 8 channels)
    float c0[8], c1[8], c2[8], c3[8], bb[8];
#pragma unroll
    for (int i = 0; i < 8; i++) {
        c0[i] = __ldg(C + 0 * DD + d0 + i);
        c1[i] = __ldg(C + 1 * DD + d0 + i);
        c2[i] = __ldg(C + 2 * DD + d0 + i);
        c3[i] = __ldg(C + 3 * DD + d0 + i);
        bb[i] = __ldg(bc + d0 + i);
    }

    for (int e = warp; e < N_EDGES; e += nwarps) {
        int s = __ldg(src + e);
        int t = __ldg(dst + e);
        float4 a = __ldg((const float4*)(ea) + e);
        const float4* hp = (const float4*)(H + (size_t)s * DD + d0);
        float4 h0 = __ldg(hp);
        float4 h1 = __ldg(hp + 1);
        float v[8];
        v[0] = h0.x; v[1] = h0.y; v[2] = h0.z; v[3] = h0.w;
        v[4] = h1.x; v[5] = h1.y; v[6] = h1.z; v[7] = h1.w;
#pragma unroll
        for (int i = 0; i < 8; i++) {
            float x = v[i] + bb[i] + a.x * c0[i] + a.y * c1[i] + a.z * c2[i] + a.w * c3[i];
            v[i] = leaky(x);
        }
        float* op = agg + (size_t)t * DD + d0;
        red_add_v4(op,     v[0], v[1], v[2], v[3]);
        red_add_v4(op + 4, v[4], v[5], v[6], v[7]);
    }
}

// ---------------- BN stats ---------------------------------------------------
__global__ void bn_stats(const float* __restrict__ X)
{
    int c = threadIdx.x;                 // channel, 256 threads
    int rows_per = (N_NODES + gridDim.x - 1) / gridDim.x;
    int r0 = blockIdx.x * rows_per;
    int r1 = min(r0 + rows_per, N_NODES);
    float s = 0.f, q = 0.f;
    for (int r = r0; r < r1; r++) {
        float v = __ldg(X + (size_t)r * DD + c);
        s += v;
        q += v * v;
    }
    atomicAdd(&g_bnsum[c], s);
    atomicAdd(&g_bnsq[c], q);
}

// ---------------- BN apply + leaky ------------------------------------------
__global__ void bn_apply(const float* __restrict__ X,
                         const float* __restrict__ w,
                         const float* __restrict__ b,
                         float* __restrict__ out)
{
    const float invN = 1.f / (float)N_NODES;
    int i = blockIdx.x * blockDim.x + threadIdx.x;
    int stride = gridDim.x * blockDim.x;
    int n4 = N_NODES * DD / 4;
    for (; i < n4; i += stride) {
        int c = (i * 4) & (DD - 1);
        float4 x = __ldg((const float4*)X + i);
        float r[4] = {x.x, x.y, x.z, x.w};
#pragma unroll
        for (int j = 0; j < 4; j++) {
            int ch = c + j;
            float m = g_bnsum[ch] * invN;
            float var = g_bnsq[ch] * invN - m * m;
            float inv = rsqrtf(var + EPS);
            float v = (r[j] - m) * inv * __ldg(w + ch) + __ldg(b + ch);
            r[j] = leaky(v);
        }
        ((float4*)out)[i] = make_float4(r[0], r[1], r[2], r[3]);
    }
}

// ---------------- gate + segment max ----------------------------------------
__global__ void gate_kernel(const float* __restrict__ x2,
                            const float* __restrict__ gw,
                            const float* __restrict__ gb,
                            const int* __restrict__ batch)
{
    int warp = (blockIdx.x * blockDim.x + threadIdx.x) >> 5;
    int lane = threadIdx.x & 31;
    if (warp >= N_NODES) return;
    int d0 = lane * 8;
    const float4* xp = (const float4*)(x2 + (size_t)warp * DD + d0);
    const float4* wp = (const float4*)(gw + d0);
    float4 a0 = __ldg(xp), a1 = __ldg(xp + 1);
    float4 b0 = __ldg(wp), b1 = __ldg(wp + 1);
    float s = a0.x * b0.x + a0.y * b0.y + a0.z * b0.z + a0.w * b0.w
            + a1.x * b1.x + a1.y * b1.y + a1.z * b1.z + a1.w * b1.w;
#pragma unroll
    for (int off = 16; off; off >>= 1) s += __shfl_xor_sync(0xffffffffu, s, off);
    if (lane == 0) {
        s += __ldg(gb);
        g_gate[warp] = s;
        atomicMax(&g_gmax[__ldg(batch + warp)], enc_f(s));
    }
}

// ---------------- exp + segment sum ------------------------------------------
__global__ void expsum_kernel(const int* __restrict__ batch)
{
    int n = blockIdx.x * blockDim.x + threadIdx.x;
    if (n >= N_NODES) return;
    int b = __ldg(batch + n);
    float gm = dec_f(g_gmax[b]);
    float e = __expf(g_gate[n] - gm);
    g_e[n] = e;
    atomicAdd(&g_denom[b], e);
}

// ---------------- final weighted aggregation ---------------------------------
__global__ void final_kernel(const float* __restrict__ x2,
                             const int* __restrict__ batch,
                             float* __restrict__ out)
{
    int warp = (blockIdx.x * blockDim.x + threadIdx.x) >> 5;
    int lane = threadIdx.x & 31;
    if (warp >= N_NODES) return;
    int b = __ldg(batch + warp);
    float w = g_e[warp] / g_denom[b];
    int d0 = lane * 8;
    const float4* xp = (const float4*)(x2 + (size_t)warp * DD + d0);
    float4 a0 = __ldg(xp), a1 = __ldg(xp + 1);
    float* op = out + (size_t)b * DD + d0;
    red_add_v4(op,     w * a0.x, w * a0.y, w * a0.z, w * a0.w);
    red_add_v4(op + 4, w * a1.x, w * a1.y, w * a1.z, w * a1.w);
}

// ---------------- launch -----------------------------------------------------
extern "C" void kernel_launch(void* const* d_in, const int* in_sizes, int n_in,
                              void* d_out, int out_size)
{
    const int*   node_ids  = (const int*)d_in[0];
    const int*   edge_index= (const int*)d_in[1];
    const float* edge_attr = (const float*)d_in[2];
    const int*   batch     = (const int*)d_in[3];
    const float* emb       = (const float*)d_in[4];
    const float* c1_lin2_w = (const float*)d_in[5];
    const float* c1_lin2_b = (const float*)d_in[6];
    const float* c1_lin_w  = (const float*)d_in[7];
    const float* c1_lin_b  = (const float*)d_in[8];
    const float* bn1_w     = (const float*)d_in[9];
    const float* bn1_b     = (const float*)d_in[10];
    const float* c2_lin2_w = (const float*)d_in[11];
    const float* c2_lin2_b = (const float*)d_in[12];
    const float* c2_lin_w  = (const float*)d_in[13];
    const float* c2_lin_b  = (const float*)d_in[14];
    const float* bn2_w     = (const float*)d_in[15];
    const float* bn2_b     = (const float*)d_in[16];
    const float* gate_w    = (const float*)d_in[17];
    const float* gate_b    = (const float*)d_in[18];
    float* out = (float*)d_out;

    const int* src = edge_index;
    const int* dst = edge_index + N_EDGES;

    float *pA, *pB, *pC, *pC1, *pbc1, *pC2, *pbc2;
    cudaGetSymbolAddress((void**)&pA,   g_bufA);
    cudaGetSymbolAddress((void**)&pB,   g_bufB);
    cudaGetSymbolAddress((void**)&pC,   g_bufC);
    cudaGetSymbolAddress((void**)&pC1,  g_C1);
    cudaGetSymbolAddress((void**)&pbc1, g_bc1);
    cudaGetSymbolAddress((void**)&pC2,  g_C2);
    cudaGetSymbolAddress((void**)&pbc2, g_bc2);

    const int ND = N_NODES * DD;

    // init
    zero_small<<<2, 512>>>();
    zero_f<<<4096, 256>>>(pB, ND);
    zero_f<<<4096, 256>>>(pC, ND);
    zero_f<<<(out_size + 255) / 256, 256>>>(out, out_size);

    // combined edge matrices
    combine_kernel<<<1, 256>>>(c1_lin2_w, c1_lin2_b, c1_lin_w, c1_lin_b,
                               c2_lin2_w, c2_lin2_b, c2_lin_w, c2_lin_b);

    // H1 = emb[node_ids] @ W1^T   -> bufA
    dim3 g1((N_NODES + 63) / 64, DD / 64);
    gemm_kernel<<<g1, 256>>>(emb, node_ids, c1_lin_w, pA, N_NODES, F_IN);

    // conv1 scatter -> bufB
    scatter_kernel<<<2048, 256>>>(pA, src, dst, edge_attr, pC1, pbc1, pB);

    // BN1 + leaky -> bufA (x1)
    bn_stats<<<512, 256>>>(pB);
    bn_apply<<<4096, 256>>>(pB, bn1_w, bn1_b, pA);

    // H2 = x1 @ W2^T -> bufB (agg1 consumed)
    gemm_kernel<<<g1, 256>>>(pA, nullptr, c2_lin_w, pB, N_NODES, DD);

    // conv2 scatter -> bufC
    scatter_kernel<<<2048, 256>>>(pB, src, dst, edge_attr, pC2, pbc2, pC);

    // BN2 + leaky -> bufA (x2)
    zero_bn<<<1, 256>>>();
    bn_stats<<<512, 256>>>(pC);
    bn_apply<<<4096, 256>>>(pC, bn2_w, bn2_b, pA);

    // attentional aggregation
    int nb = (N_NODES * 32 + 255) / 256;
    gate_kernel<<<nb, 256>>>(pA, gate_w, gate_b, batch);
    expsum_kernel<<<(N_NODES + 255) / 256, 256>>>(batch);
    final_kernel<<<nb, 256>>>(pA, batch, out);
}

// round 2
// speedup vs baseline: 1.6453x; 1.6453x over previous
#include <cuda_runtime.h>
#include <cstdint>

#define N_NODES  50000
#define N_EDGES  800000
#define N_GRAPHS 512
#define F_IN     128
#define DD       256
#define EPS      1e-5f
#define NEG_SLOPE 0.01f
#define NSB      196          // ceil(N_NODES/256) scan blocks

// ---------------- scratch (device globals; no allocation allowed) ----------
__device__ float g_bufA[N_NODES * DD];   // H1 -> H2
__device__ float g_bufB[N_NODES * DD];   // agg1 -> agg2 -> x2 (in place)
__device__ float g_C1[4 * DD];
__device__ float g_bc1[DD];
__device__ float g_C2[4 * DD];
__device__ float g_bc2[DD];
__device__ float g_bnsum[DD];
__device__ float g_bnsq[DD];
__device__ float g_sc[DD];
__device__ float g_sh[DD];
__device__ unsigned g_gmax[N_GRAPHS];
__device__ float g_denom[N_GRAPHS];
__device__ float g_gate[N_NODES];
__device__ float g_e[N_NODES];
// CSR
__device__ int g_deg[N_NODES];
__device__ int g_start[N_NODES];
__device__ int g_cursor[N_NODES];
__device__ int g_eid[N_EDGES];
__device__ int g_part[NSB];
__device__ int g_part2[NSB];

// ---------------- helpers ---------------------------------------------------
__device__ __forceinline__ float leaky(float v) {
    return v >= 0.f ? v : NEG_SLOPE * v;
}
__device__ __forceinline__ unsigned enc_f(float x) {
    unsigned u = __float_as_uint(x);
    return (u & 0x80000000u) ? ~u : (u | 0x80000000u);
}
__device__ __forceinline__ float dec_f(unsigned u) {
    return (u & 0x80000000u) ? __uint_as_float(u ^ 0x80000000u) : __uint_as_float(~u);
}
__device__ __forceinline__ void red_add_v4(float* p, float a, float b, float c, float d) {
    asm volatile("red.global.add.v4.f32 [%0], {%1, %2, %3, %4};"
                 :: "l"(p), "f"(a), "f"(b), "f"(c), "f"(d) : "memory");
}
__device__ __forceinline__ unsigned long long dup2(float x) {
    unsigned long long r; unsigned u = __float_as_uint(x);
    asm("mov.b64 %0, {%1, %1};" : "=l"(r) : "r"(u));
    return r;
}
__device__ __forceinline__ void fma2(unsigned long long& d, unsigned long long a, unsigned long long b) {
    asm("fma.rn.f32x2 %0, %1, %2, %0;" : "+l"(d) : "l"(a), "l"(b));
}
__device__ __forceinline__ float2 up2(unsigned long long v) {
    float2 f; asm("mov.b64 {%0, %1}, %2;" : "=f"(f.x), "=f"(f.y) : "l"(v));
    return f;
}

// ---------------- zero / init kernels ---------------------------------------
__global__ void zero_f(float* p, int n) {
    int i = blockIdx.x * blockDim.x + threadIdx.x;
    int stride = gridDim.x * blockDim.x;
    for (; i < n; i += stride) p[i] = 0.f;
}
__global__ void zero_small() {
    int t = blockIdx.x * blockDim.x + threadIdx.x;
    if (t < DD) { g_bnsum[t] = 0.f; g_bnsq[t] = 0.f; }
    if (t < N_GRAPHS) { g_gmax[t] = 0u; g_denom[t] = 0.f; }
}
__global__ void zero_bn() {
    int t = threadIdx.x;
    if (t < DD) { g_bnsum[t] = 0.f; g_bnsq[t] = 0.f; }
}
__global__ void zero_deg() {
    int i = blockIdx.x * blockDim.x + threadIdx.x;
    if (i < N_NODES) g_deg[i] = 0;
}

// ---------------- CSR build --------------------------------------------------
__global__ void hist_kernel(const int* __restrict__ dst) {
    int e = blockIdx.x * blockDim.x + threadIdx.x;
    if (e < N_EDGES) atomicAdd(&g_deg[__ldg(dst + e)], 1);
}
__global__ void scan1_kernel() {
    __shared__ int sh[256];
    int i = blockIdx.x * 256 + threadIdx.x;
    int v = (i < N_NODES) ? g_deg[i] : 0;
    sh[threadIdx.x] = v; __syncthreads();
#pragma unroll
    for (int off = 1; off < 256; off <<= 1) {
        int tv = (threadIdx.x >= off) ? sh[threadIdx.x - off] : 0;
        __syncthreads();
        sh[threadIdx.x] += tv;
        __syncthreads();
    }
    if (i < N_NODES) g_start[i] = sh[threadIdx.x] - v;   // block-local exclusive
    if (threadIdx.x == 255) g_part[blockIdx.x] = sh[255];
}
__global__ void scan2_kernel() {
    __shared__ int sh[256];
    int t = threadIdx.x;
    int v = (t < NSB) ? g_part[t] : 0;
    sh[t] = v; __syncthreads();
#pragma unroll
    for (int off = 1; off < 256; off <<= 1) {
        int tv = (t >= off) ? sh[t - off] : 0;
        __syncthreads();
        sh[t] += tv;
        __syncthreads();
    }
    if (t < NSB) g_part2[t] = sh[t] - v;                 // exclusive
}
__global__ void scan3_kernel() {
    int i = blockIdx.x * 256 + threadIdx.x;
    if (i < N_NODES) {
        int s = g_start[i] + g_part2[blockIdx.x];
        g_start[i] = s;
        g_cursor[i] = s;
    }
}
__global__ void fill_kernel(const int* __restrict__ dst) {
    int e = blockIdx.x * blockDim.x + threadIdx.x;
    if (e < N_EDGES) {
        int d = __ldg(dst + e);
        int p = atomicAdd(&g_cursor[d], 1);
        g_eid[p] = e;
    }
}

// ---------------- combined edge matrices ------------------------------------
__global__ void combine_kernel(
    const float* __restrict__ l2w1, const float* __restrict__ l2b1,
    const float* __restrict__ lw1,  const float* __restrict__ lb1,
    const float* __restrict__ l2w2, const float* __restrict__ l2b2,
    const float* __restrict__ lw2,  const float* __restrict__ lb2)
{
    int d = threadIdx.x;   // 256 threads
    {
        float a0 = 0.f, a1 = 0.f, a2 = 0.f, a3 = 0.f, bb = 0.f;
        for (int f = 0; f < F_IN; f++) {
            float w = lw1[d * F_IN + f];
            float4 l2 = *(const float4*)(l2w1 + f * 4);
            a0 += l2.x * w; a1 += l2.y * w; a2 += l2.z * w; a3 += l2.w * w;
            bb += l2b1[f] * w;
        }
        g_C1[0 * DD + d] = a0; g_C1[1 * DD + d] = a1;
        g_C1[2 * DD + d] = a2; g_C1[3 * DD + d] = a3;
        g_bc1[d] = bb + lb1[d];
    }
    {
        float a0 = 0.f, a1 = 0.f, a2 = 0.f, a3 = 0.f, bb = 0.f;
        for (int f = 0; f < DD; f++) {
            float w = lw2[d * DD + f];
            float4 l2 = *(const float4*)(l2w2 + f * 4);
            a0 += l2.x * w; a1 += l2.y * w; a2 += l2.z * w; a3 += l2.w * w;
            bb += l2b2[f] * w;
        }
        g_C2[0 * DD + d] = a0; g_C2[1 * DD + d] = a1;
        g_C2[2 * DD + d] = a2; g_C2[3 * DD + d] = a3;
        g_bc2[d] = bb + lb2[d];
    }
}

// ---------------- GEMM (f32x2 packed): out[m][n] = sum_k A'[m][k] W[n][k] ---
// A' = leaky(A*sc + sh) when sc != null (fused BN+leaky on the input side).
// Tile 128x128, BK=8, 256 threads, 8x8 micro-tile, FMA via fma.rn.f32x2.
__global__ void gemm_f32x2(const float* __restrict__ A, const int* __restrict__ idx,
                           const float* __restrict__ sc, const float* __restrict__ sh,
                           const float* __restrict__ W, float* __restrict__ out,
                           int M, int K)
{
    __shared__ unsigned long long As2[8][128];  // pre-duplicated A pairs (8 KB)
    __shared__ float Bs[8][128];                // 4 KB
    int t = threadIdx.x;
    int bm = blockIdx.x * 128;
    int bn = blockIdx.y * 128;
    int tx = t & 15, ty = t >> 4;
    int lr = t >> 1;            // 0..127
    int lk = (t & 1) * 4;       // 0 or 4

    unsigned long long acc[8][4];
#pragma unroll
    for (int i = 0; i < 8; i++)
#pragma unroll
        for (int j = 0; j < 4; j++) acc[i][j] = 0ull;

    int m0 = bm + lr;
    int mc = m0 < M ? m0 : (M - 1);
    int arow = idx ? __ldg(idx + mc) : mc;
    const float* Arow = A + (size_t)arow * K;
    const float* Wrow = W + (size_t)(bn + lr) * K;

    for (int k0 = 0; k0 < K; k0 += 8) {
        float4 av = __ldg((const float4*)(Arow + k0 + lk));
        if (sc) {
            float4 scv = __ldg((const float4*)(sc + k0 + lk));
            float4 shv = __ldg((const float4*)(sh + k0 + lk));
            av.x = leaky(av.x * scv.x + shv.x);
            av.y = leaky(av.y * scv.y + shv.y);
            av.z = leaky(av.z * scv.z + shv.z);
            av.w = leaky(av.w * scv.w + shv.w);
        }
        As2[lk + 0][lr] = dup2(av.x);
        As2[lk + 1][lr] = dup2(av.y);
        As2[lk + 2][lr] = dup2(av.z);
        As2[lk + 3][lr] = dup2(av.w);
        float4 wv = __ldg((const float4*)(Wrow + k0 + lk));
        Bs[lk + 0][lr] = wv.x;
        Bs[lk + 1][lr] = wv.y;
        Bs[lk + 2][lr] = wv.z;
        Bs[lk + 3][lr] = wv.w;
        __syncthreads();
#pragma unroll
        for (int kk = 0; kk < 8; kk++) {
            ulonglong2 p0 = *(const ulonglong2*)&As2[kk][ty * 8 + 0];
            ulonglong2 p1 = *(const ulonglong2*)&As2[kk][ty * 8 + 2];
            ulonglong2 p2 = *(const ulonglong2*)&As2[kk][ty * 8 + 4];
            ulonglong2 p3 = *(const ulonglong2*)&As2[kk][ty * 8 + 6];
            ulonglong2 q0 = *(const ulonglong2*)&Bs[kk][tx * 8 + 0];
            ulonglong2 q1 = *(const ulonglong2*)&Bs[kk][tx * 8 + 4];
            unsigned long long a2[8] = {p0.x, p0.y, p1.x, p1.y, p2.x, p2.y, p3.x, p3.y};
            unsigned long long b2[4] = {q0.x, q0.y, q1.x, q1.y};
#pragma unroll
            for (int i = 0; i < 8; i++)
#pragma unroll
                for (int j = 0; j < 4; j++) fma2(acc[i][j], a2[i], b2[j]);
        }
        __syncthreads();
    }
#pragma unroll
    for (int i = 0; i < 8; i++) {
        int m = bm + ty * 8 + i;
        if (m < M) {
            float2 r0 = up2(acc[i][0]), r1 = up2(acc[i][1]);
            float2 r2 = up2(acc[i][2]), r3 = up2(acc[i][3]);
            float* op = out + (size_t)m * DD + bn + tx * 8;
            *(float4*)(op)     = make_float4(r0.x, r0.y, r1.x, r1.y);
            *(float4*)(op + 4) = make_float4(r2.x, r2.y, r3.x, r3.y);
        }
    }
}

// ---------------- CSR gather: agg[n] = sum_{e: dst=n} leaky(H[src]+ea@C+bc) -
// Also accumulates BN sum/sumsq per channel (registers -> smem -> global).
__global__ void gather_kernel(const float* __restrict__ H,
                              const int* __restrict__ src,
                              const float* __restrict__ ea,
                              const float* __restrict__ C,
                              const float* __restrict__ bc,
                              float* __restrict__ agg)
{
    __shared__ float ssum[DD];
    __shared__ float ssq[DD];
    int t = threadIdx.x;
    ssum[t] = 0.f; ssq[t] = 0.f;
    __syncthreads();

    int lane = t & 31;
    int wid = (blockIdx.x * blockDim.x + t) >> 5;
    int nw = (gridDim.x * blockDim.x) >> 5;
    int d0 = lane * 8;

    float c0[8], c1[8], c2[8], c3[8], bb[8];
#pragma unroll
    for (int i = 0; i < 8; i++) {
        c0[i] = __ldg(C + 0 * DD + d0 + i);
        c1[i] = __ldg(C + 1 * DD + d0 + i);
        c2[i] = __ldg(C + 2 * DD + d0 + i);
        c3[i] = __ldg(C + 3 * DD + d0 + i);
        bb[i] = __ldg(bc + d0 + i);
    }

    float sA[8], qA[8];
#pragma unroll
    for (int i = 0; i < 8; i++) { sA[i] = 0.f; qA[i] = 0.f; }

    for (int n = wid; n < N_NODES; n += nw) {
        int s0 = __ldg(g_start + n);
        int dg = __ldg(g_deg + n);
        float v[8];
#pragma unroll
        for (int i = 0; i < 8; i++) v[i] = 0.f;

        int e = 0, sn = 0;
        if (dg > 0) { e = __ldg(g_eid + s0); sn = __ldg(src + e); }
        for (int j = 0; j < dg; j++) {
            int ecur = e, scur = sn;
            if (j + 1 < dg) e = __ldg(g_eid + s0 + j + 1);
            float4 a = __ldg((const float4*)ea + ecur);
            const float4* hp = (const float4*)(H + (size_t)scur * DD + d0);
            float4 h0 = __ldg(hp);
            float4 h1 = __ldg(hp + 1);
            if (j + 1 < dg) sn = __ldg(src + e);
            float hv[8] = {h0.x, h0.y, h0.z, h0.w, h1.x, h1.y, h1.z, h1.w};
#pragma unroll
            for (int i = 0; i < 8; i++) {
                float x = hv[i] + bb[i] + a.x * c0[i] + a.y * c1[i] + a.z * c2[i] + a.w * c3[i];
                v[i] += leaky(x);
            }
        }
        float* op = agg + (size_t)n * DD + d0;
        *(float4*)(op)     = make_float4(v[0], v[1], v[2], v[3]);
        *(float4*)(op + 4) = make_float4(v[4], v[5], v[6], v[7]);
#pragma unroll
        for (int i = 0; i < 8; i++) { sA[i] += v[i]; qA[i] += v[i] * v[i]; }
    }
#pragma unroll
    for (int i = 0; i < 8; i++) {
        atomicAdd(&ssum[d0 + i], sA[i]);
        atomicAdd(&ssq[d0 + i], qA[i]);
    }
    __syncthreads();
    atomicAdd(&g_bnsum[t], ssum[t]);
    atomicAdd(&g_bnsq[t], ssq[t]);
}

// ---------------- BN scale/shift from stats ----------------------------------
__global__ void bnsc_kernel(const float* __restrict__ w, const float* __restrict__ b)
{
    int c = threadIdx.x;
    const float invN = 1.f / (float)N_NODES;
    float m = g_bnsum[c] * invN;
    float var = g_bnsq[c] * invN - m * m;
    float s = w[c] * rsqrtf(var + EPS);
    g_sc[c] = s;
    g_sh[c] = b[c] - m * s;
}

// ---------------- BN2 apply + leaky (in place) + gate + segment max ----------
__global__ void bn_apply_gate(float* __restrict__ X,
                              const float* __restrict__ gw,
                              const float* __restrict__ gb,
                              const int* __restrict__ batch)
{
    int wid = (blockIdx.x * blockDim.x + threadIdx.x) >> 5;
    int lane = threadIdx.x & 31;
    if (wid >= N_NODES) return;
    int d0 = lane * 8;
    float4* xp = (float4*)(X + (size_t)wid * DD + d0);
    float4 h0 = xp[0], h1 = xp[1];
    float v[8] = {h0.x, h0.y, h0.z, h0.w, h1.x, h1.y, h1.z, h1.w};
    float gsum = 0.f;
#pragma unroll
    for (int i = 0; i < 8; i++) {
        int ch = d0 + i;
        float x = leaky(v[i] * g_sc[ch] + g_sh[ch]);
        v[i] = x;
        gsum += x * __ldg(gw + ch);
    }
    xp[0] = make_float4(v[0], v[1], v[2], v[3]);
    xp[1] = make_float4(v[4], v[5], v[6], v[7]);
#pragma unroll
    for (int off = 16; off; off >>= 1) gsum += __shfl_xor_sync(0xffffffffu, gsum, off);
    if (lane == 0) {
        gsum += __ldg(gb);
        g_gate[wid] = gsum;
        atomicMax(&g_gmax[__ldg(batch + wid)], enc_f(gsum));
    }
}

// ---------------- exp + segment sum ------------------------------------------
__global__ void expsum_kernel(const int* __restrict__ batch)
{
    int n = blockIdx.x * blockDim.x + threadIdx.x;
    if (n >= N_NODES) return;
    int b = __ldg(batch + n);
    float gm = dec_f(g_gmax[b]);
    float e = __expf(g_gate[n] - gm);
    g_e[n] = e;
    atomicAdd(&g_denom[b], e);
}

// ---------------- final weighted aggregation ---------------------------------
__global__ void final_kernel(const float* __restrict__ x2,
                             const int* __restrict__ batch,
                             float* __restrict__ out)
{
    int wid = (blockIdx.x * blockDim.x + threadIdx.x) >> 5;
    int lane = threadIdx.x & 31;
    if (wid >= N_NODES) return;
    int b = __ldg(batch + wid);
    float w = g_e[wid] / g_denom[b];
    int d0 = lane * 8;
    const float4* xp = (const float4*)(x2 + (size_t)wid * DD + d0);
    float4 a0 = __ldg(xp), a1 = __ldg(xp + 1);
    float* op = out + (size_t)b * DD + d0;
    red_add_v4(op,     w * a0.x, w * a0.y, w * a0.z, w * a0.w);
    red_add_v4(op + 4, w * a1.x, w * a1.y, w * a1.z, w * a1.w);
}

// ---------------- launch -----------------------------------------------------
extern "C" void kernel_launch(void* const* d_in, const int* in_sizes, int n_in,
                              void* d_out, int out_size)
{
    const int*   node_ids  = (const int*)d_in[0];
    const int*   edge_index= (const int*)d_in[1];
    const float* edge_attr = (const float*)d_in[2];
    const int*   batch     = (const int*)d_in[3];
    const float* emb       = (const float*)d_in[4];
    const float* c1_lin2_w = (const float*)d_in[5];
    const float* c1_lin2_b = (const float*)d_in[6];
    const float* c1_lin_w  = (const float*)d_in[7];
    const float* c1_lin_b  = (const float*)d_in[8];
    const float* bn1_w     = (const float*)d_in[9];
    const float* bn1_b     = (const float*)d_in[10];
    const float* c2_lin2_w = (const float*)d_in[11];
    const float* c2_lin2_b = (const float*)d_in[12];
    const float* c2_lin_w  = (const float*)d_in[13];
    const float* c2_lin_b  = (const float*)d_in[14];
    const float* bn2_w     = (const float*)d_in[15];
    const float* bn2_b     = (const float*)d_in[16];
    const float* gate_w    = (const float*)d_in[17];
    const float* gate_b    = (const float*)d_in[18];
    float* out = (float*)d_out;

    const int* src = edge_index;
    const int* dst = edge_index + N_EDGES;

    float *pA, *pB, *pC1, *pbc1, *pC2, *pbc2, *psc, *psh;
    cudaGetSymbolAddress((void**)&pA,   g_bufA);
    cudaGetSymbolAddress((void**)&pB,   g_bufB);
    cudaGetSymbolAddress((void**)&pC1,  g_C1);
    cudaGetSymbolAddress((void**)&pbc1, g_bc1);
    cudaGetSymbolAddress((void**)&pC2,  g_C2);
    cudaGetSymbolAddress((void**)&pbc2, g_bc2);
    cudaGetSymbolAddress((void**)&psc,  g_sc);
    cudaGetSymbolAddress((void**)&psh,  g_sh);

    // ---- init ----
    zero_small<<<2, 512>>>();
    zero_deg<<<NSB, 256>>>();
    zero_f<<<(out_size + 255) / 256, 256>>>(out, out_size);

    // ---- CSR build (dst-sorted edge ids) ----
    hist_kernel<<<(N_EDGES + 255) / 256, 256>>>(dst);
    scan1_kernel<<<NSB, 256>>>();
    scan2_kernel<<<1, 256>>>();
    scan3_kernel<<<NSB, 256>>>();
    fill_kernel<<<(N_EDGES + 255) / 256, 256>>>(dst);

    // ---- combined edge matrices ----
    combine_kernel<<<1, 256>>>(c1_lin2_w, c1_lin2_b, c1_lin_w, c1_lin_b,
                               c2_lin2_w, c2_lin2_b, c2_lin_w, c2_lin_b);

    dim3 gg((N_NODES + 127) / 128, DD / 128);

    // ---- layer 1: H1 = emb[node_ids] @ W1^T ----
    gemm_f32x2<<<gg, 256>>>(emb, node_ids, nullptr, nullptr, c1_lin_w, pA, N_NODES, F_IN);

    // ---- conv1 gather -> agg1 (bufB) + bn1 stats ----
    gather_kernel<<<2048, 256>>>(pA, src, edge_attr, pC1, pbc1, pB);
    bnsc_kernel<<<1, 256>>>(bn1_w, bn1_b);

    // ---- layer 2: H2 = leaky(bn1(agg1)) @ W2^T  (BN fused into A-load) ----
    gemm_f32x2<<<gg, 256>>>(pB, nullptr, psc, psh, c2_lin_w, pA, N_NODES, DD);

    // ---- conv2 gather -> agg2 (bufB) + bn2 stats ----
    zero_bn<<<1, 256>>>();
    gather_kernel<<<2048, 256>>>(pA, src, edge_attr, pC2, pbc2, pB);
    bnsc_kernel<<<1, 256>>>(bn2_w, bn2_b);

    // ---- bn2 apply (in place) + gate + segment max ----
    int nb = (N_NODES * 32 + 255) / 256;
    bn_apply_gate<<<nb, 256>>>(pB, gate_w, gate_b, batch);

    // ---- softmax + weighted aggregation ----
    expsum_kernel<<<(N_NODES + 255) / 256, 256>>>(batch);
    final_kernel<<<nb, 256>>>(pB, batch, out);
}

// round 3
// speedup vs baseline: 1.8014x; 1.0949x over previous
#include <cuda_runtime.h>
#include <cstdint>

#define N_NODES  50000
#define N_EDGES  800000
#define N_GRAPHS 512
#define F_IN     128
#define DD       256
#define EPS      1e-5f
#define NEG_SLOPE 0.01f
#define NSB      196          // ceil(N_NODES/256) scan blocks

typedef unsigned long long ull;

// ---------------- scratch (device globals; no allocation allowed) ----------
__device__ float g_bufA[N_NODES * DD];   // H1 -> H2
__device__ float g_bufB[N_NODES * DD];   // agg1 -> agg2 -> x2 (in place)
__device__ float g_C1[4 * DD];
__device__ float g_bc1[DD];
__device__ float g_C2[4 * DD];
__device__ float g_bc2[DD];
__device__ float g_bnsum[DD];
__device__ float g_bnsq[DD];
__device__ float g_sc[DD];
__device__ float g_sh[DD];
__device__ unsigned g_gmax[N_GRAPHS];
__device__ float g_denom[N_GRAPHS];
__device__ float g_gate[N_NODES];
__device__ float g_e[N_NODES];
// CSR
__device__ int g_deg[N_NODES];
__device__ int g_start[N_NODES];
__device__ int g_cursor[N_NODES];
__device__ int g_eid[N_EDGES];
__device__ int g_part[NSB];
__device__ int g_part2[NSB];

// ---------------- helpers ---------------------------------------------------
__device__ __forceinline__ float leaky(float v) {
    return v >= 0.f ? v : NEG_SLOPE * v;
}
__device__ __forceinline__ unsigned enc_f(float x) {
    unsigned u = __float_as_uint(x);
    return (u & 0x80000000u) ? ~u : (u | 0x80000000u);
}
__device__ __forceinline__ float dec_f(unsigned u) {
    return (u & 0x80000000u) ? __uint_as_float(u ^ 0x80000000u) : __uint_as_float(~u);
}
__device__ __forceinline__ void red_add_v4(float* p, float a, float b, float c, float d) {
    asm volatile("red.global.add.v4.f32 [%0], {%1, %2, %3, %4};"
                 :: "l"(p), "f"(a), "f"(b), "f"(c), "f"(d) : "memory");
}
__device__ __forceinline__ ull dup2(float x) {
    ull r; unsigned u = __float_as_uint(x);
    asm("mov.b64 %0, {%1, %1};" : "=l"(r) : "r"(u));
    return r;
}
// d = a*b + d (packed pair)
__device__ __forceinline__ void fma2(ull& d, ull a, ull b) {
    asm("fma.rn.f32x2 %0, %1, %2, %0;" : "+l"(d) : "l"(a), "l"(b));
}
__device__ __forceinline__ ull add2(ull a, ull b) {
    ull r;
    asm("add.rn.f32x2 %0, %1, %2;" : "=l"(r) : "l"(a), "l"(b));
    return r;
}
__device__ __forceinline__ float2 up2(ull v) {
    float2 f; asm("mov.b64 {%0, %1}, %2;" : "=f"(f.x), "=f"(f.y) : "l"(v));
    return f;
}

// ---------------- zero / init kernels ---------------------------------------
__global__ void zero_f(float* p, int n) {
    int i = blockIdx.x * blockDim.x + threadIdx.x;
    int stride = gridDim.x * blockDim.x;
    for (; i < n; i += stride) p[i] = 0.f;
}
__global__ void zero_small() {
    int t = blockIdx.x * blockDim.x + threadIdx.x;
    if (t < DD) { g_bnsum[t] = 0.f; g_bnsq[t] = 0.f; }
    if (t < N_GRAPHS) { g_gmax[t] = 0u; g_denom[t] = 0.f; }
}
__global__ void zero_bn() {
    int t = threadIdx.x;
    if (t < DD) { g_bnsum[t] = 0.f; g_bnsq[t] = 0.f; }
}
__global__ void zero_deg() {
    int i = blockIdx.x * blockDim.x + threadIdx.x;
    if (i < N_NODES) g_deg[i] = 0;
}

// ---------------- CSR build --------------------------------------------------
__global__ void hist_kernel(const int* __restrict__ dst) {
    int e = blockIdx.x * blockDim.x + threadIdx.x;
    if (e < N_EDGES) atomicAdd(&g_deg[__ldg(dst + e)], 1);
}
__global__ void scan1_kernel() {
    __shared__ int sh[256];
    int i = blockIdx.x * 256 + threadIdx.x;
    int v = (i < N_NODES) ? g_deg[i] : 0;
    sh[threadIdx.x] = v; __syncthreads();
#pragma unroll
    for (int off = 1; off < 256; off <<= 1) {
        int tv = (threadIdx.x >= off) ? sh[threadIdx.x - off] : 0;
        __syncthreads();
        sh[threadIdx.x] += tv;
        __syncthreads();
    }
    if (i < N_NODES) g_start[i] = sh[threadIdx.x] - v;   // block-local exclusive
    if (threadIdx.x == 255) g_part[blockIdx.x] = sh[255];
}
__global__ void scan2_kernel() {
    __shared__ int sh[256];
    int t = threadIdx.x;
    int v = (t < NSB) ? g_part[t] : 0;
    sh[t] = v; __syncthreads();
#pragma unroll
    for (int off = 1; off < 256; off <<= 1) {
        int tv = (t >= off) ? sh[t - off] : 0;
        __syncthreads();
        sh[t] += tv;
        __syncthreads();
    }
    if (t < NSB) g_part2[t] = sh[t] - v;                 // exclusive
}
__global__ void scan3_kernel() {
    int i = blockIdx.x * 256 + threadIdx.x;
    if (i < N_NODES) {
        int s = g_start[i] + g_part2[blockIdx.x];
        g_start[i] = s;
        g_cursor[i] = s;
    }
}
__global__ void fill_kernel(const int* __restrict__ dst) {
    int e = blockIdx.x * blockDim.x + threadIdx.x;
    if (e < N_EDGES) {
        int d = __ldg(dst + e);
        int p = atomicAdd(&g_cursor[d], 1);
        g_eid[p] = e;
    }
}

// ---------------- combined edge matrices ------------------------------------
__global__ void combine_kernel(
    const float* __restrict__ l2w1, const float* __restrict__ l2b1,
    const float* __restrict__ lw1,  const float* __restrict__ lb1,
    const float* __restrict__ l2w2, const float* __restrict__ l2b2,
    const float* __restrict__ lw2,  const float* __restrict__ lb2)
{
    int d = threadIdx.x;   // 256 threads
    {
        float a0 = 0.f, a1 = 0.f, a2 = 0.f, a3 = 0.f, bb = 0.f;
        for (int f = 0; f < F_IN; f++) {
            float w = lw1[d * F_IN + f];
            float4 l2 = *(const float4*)(l2w1 + f * 4);
            a0 += l2.x * w; a1 += l2.y * w; a2 += l2.z * w; a3 += l2.w * w;
            bb += l2b1[f] * w;
        }
        g_C1[0 * DD + d] = a0; g_C1[1 * DD + d] = a1;
        g_C1[2 * DD + d] = a2; g_C1[3 * DD + d] = a3;
        g_bc1[d] = bb + lb1[d];
    }
    {
        float a0 = 0.f, a1 = 0.f, a2 = 0.f, a3 = 0.f, bb = 0.f;
        for (int f = 0; f < DD; f++) {
            float w = lw2[d * DD + f];
            float4 l2 = *(const float4*)(l2w2 + f * 4);
            a0 += l2.x * w; a1 += l2.y * w; a2 += l2.z * w; a3 += l2.w * w;
            bb += l2b2[f] * w;
        }
        g_C2[0 * DD + d] = a0; g_C2[1 * DD + d] = a1;
        g_C2[2 * DD + d] = a2; g_C2[3 * DD + d] = a3;
        g_bc2[d] = bb + lb2[d];
    }
}

// ---------------- GEMM (f32x2, reg-staged double buffer) --------------------
// out[m][n] = sum_k A'[m][k] * W[n][k];  A' = leaky(A*sc + sh) if sc != null.
// Tile 128x128, BK=16, 256 threads, 8x8 micro-tile.
__global__ void __launch_bounds__(256, 2)
gemm_f32x2(const float* __restrict__ A, const int* __restrict__ idx,
           const float* __restrict__ sc, const float* __restrict__ sh,
           const float* __restrict__ W, float* __restrict__ out,
           int M, int K)
{
    __shared__ ull   As2[16][128];   // pre-duplicated A pairs (16 KB)
    __shared__ float Bs[16][128];    // 8 KB
    int t = threadIdx.x;
    int bm = blockIdx.x * 128;
    int bn = blockIdx.y * 128;
    int tx = t & 15, ty = t >> 4;
    int lr = t >> 1;            // 0..127
    int lk = (t & 1) * 8;       // 0 or 8

    ull acc[8][4];
#pragma unroll
    for (int i = 0; i < 8; i++)
#pragma unroll
        for (int j = 0; j < 4; j++) acc[i][j] = 0ull;

    int m0 = bm + lr;
    int mc = m0 < M ? m0 : (M - 1);
    int arow = idx ? __ldg(idx + mc) : mc;
    const float* Arow = A + (size_t)arow * K;
    const float* Wrow = W + (size_t)(bn + lr) * K;

    float4 a0, a1, w0, w1;

    // ---- prologue: load tile 0 ----
    {
        a0 = __ldg((const float4*)(Arow + lk));
        a1 = __ldg((const float4*)(Arow + lk + 4));
        w0 = __ldg((const float4*)(Wrow + lk));
        w1 = __ldg((const float4*)(Wrow + lk + 4));
        if (sc) {
            float4 s0 = __ldg((const float4*)(sc + lk));
            float4 s1 = __ldg((const float4*)(sc + lk + 4));
            float4 h0 = __ldg((const float4*)(sh + lk));
            float4 h1 = __ldg((const float4*)(sh + lk + 4));
            a0.x = leaky(a0.x * s0.x + h0.x); a0.y = leaky(a0.y * s0.y + h0.y);
            a0.z = leaky(a0.z * s0.z + h0.z); a0.w = leaky(a0.w * s0.w + h0.w);
            a1.x = leaky(a1.x * s1.x + h1.x); a1.y = leaky(a1.y * s1.y + h1.y);
            a1.z = leaky(a1.z * s1.z + h1.z); a1.w = leaky(a1.w * s1.w + h1.w);
        }
        As2[lk + 0][lr] = dup2(a0.x); As2[lk + 1][lr] = dup2(a0.y);
        As2[lk + 2][lr] = dup2(a0.z); As2[lk + 3][lr] = dup2(a0.w);
        As2[lk + 4][lr] = dup2(a1.x); As2[lk + 5][lr] = dup2(a1.y);
        As2[lk + 6][lr] = dup2(a1.z); As2[lk + 7][lr] = dup2(a1.w);
        Bs[lk + 0][lr] = w0.x; Bs[lk + 1][lr] = w0.y;
        Bs[lk + 2][lr] = w0.z; Bs[lk + 3][lr] = w0.w;
        Bs[lk + 4][lr] = w1.x; Bs[lk + 5][lr] = w1.y;
        Bs[lk + 6][lr] = w1.z; Bs[lk + 7][lr] = w1.w;
    }
    __syncthreads();

    for (int k0 = 0; k0 < K; k0 += 16) {
        bool more = (k0 + 16) < K;
        if (more) {
            int kn = k0 + 16;
            a0 = __ldg((const float4*)(Arow + kn + lk));
            a1 = __ldg((const float4*)(Arow + kn + lk + 4));
            w0 = __ldg((const float4*)(Wrow + kn + lk));
            w1 = __ldg((const float4*)(Wrow + kn + lk + 4));
            if (sc) {
                float4 s0 = __ldg((const float4*)(sc + kn + lk));
                float4 s1 = __ldg((const float4*)(sc + kn + lk + 4));
                float4 h0 = __ldg((const float4*)(sh + kn + lk));
                float4 h1 = __ldg((const float4*)(sh + kn + lk + 4));
                a0.x = leaky(a0.x * s0.x + h0.x); a0.y = leaky(a0.y * s0.y + h0.y);
                a0.z = leaky(a0.z * s0.z + h0.z); a0.w = leaky(a0.w * s0.w + h0.w);
                a1.x = leaky(a1.x * s1.x + h1.x); a1.y = leaky(a1.y * s1.y + h1.y);
                a1.z = leaky(a1.z * s1.z + h1.z); a1.w = leaky(a1.w * s1.w + h1.w);
            }
        }
#pragma unroll
        for (int kk = 0; kk < 16; kk++) {
            ulonglong2 p0 = *(const ulonglong2*)&As2[kk][ty * 8 + 0];
            ulonglong2 p1 = *(const ulonglong2*)&As2[kk][ty * 8 + 2];
            ulonglong2 p2 = *(const ulonglong2*)&As2[kk][ty * 8 + 4];
            ulonglong2 p3 = *(const ulonglong2*)&As2[kk][ty * 8 + 6];
            ulonglong2 q0 = *(const ulonglong2*)&Bs[kk][tx * 8 + 0];
            ulonglong2 q1 = *(const ulonglong2*)&Bs[kk][tx * 8 + 4];
            ull a2[8] = {p0.x, p0.y, p1.x, p1.y, p2.x, p2.y, p3.x, p3.y};
            ull b2[4] = {q0.x, q0.y, q1.x, q1.y};
#pragma unroll
            for (int i = 0; i < 8; i++)
#pragma unroll
                for (int j = 0; j < 4; j++) fma2(acc[i][j], a2[i], b2[j]);
        }
        if (more) {
            __syncthreads();
            As2[lk + 0][lr] = dup2(a0.x); As2[lk + 1][lr] = dup2(a0.y);
            As2[lk + 2][lr] = dup2(a0.z); As2[lk + 3][lr] = dup2(a0.w);
            As2[lk + 4][lr] = dup2(a1.x); As2[lk + 5][lr] = dup2(a1.y);
            As2[lk + 6][lr] = dup2(a1.z); As2[lk + 7][lr] = dup2(a1.w);
            Bs[lk + 0][lr] = w0.x; Bs[lk + 1][lr] = w0.y;
            Bs[lk + 2][lr] = w0.z; Bs[lk + 3][lr] = w0.w;
            Bs[lk + 4][lr] = w1.x; Bs[lk + 5][lr] = w1.y;
            Bs[lk + 6][lr] = w1.z; Bs[lk + 7][lr] = w1.w;
            __syncthreads();
        }
    }
#pragma unroll
    for (int i = 0; i < 8; i++) {
        int m = bm + ty * 8 + i;
        if (m < M) {
            float2 r0 = up2(acc[i][0]), r1 = up2(acc[i][1]);
            float2 r2 = up2(acc[i][2]), r3 = up2(acc[i][3]);
            float* op = out + (size_t)m * DD + bn + tx * 8;
            *(float4*)(op)     = make_float4(r0.x, r0.y, r1.x, r1.y);
            *(float4*)(op + 4) = make_float4(r2.x, r2.y, r3.x, r3.y);
        }
    }
}

// ---------------- CSR gather (packed f32x2, unroll-2) ------------------------
// agg[n] = sum_{e: dst=n} leaky(H[src]+ea@C+bc);  leaky(x)=0.505x+0.495|x|
// Also accumulates BN sum/sumsq per channel.
__global__ void gather_kernel(const float* __restrict__ H,
                              const int* __restrict__ src,
                              const float* __restrict__ ea,
                              const float* __restrict__ C,
                              const float* __restrict__ bc,
                              float* __restrict__ agg)
{
    __shared__ float ssum[DD];
    __shared__ float ssq[DD];
    int t = threadIdx.x;
    ssum[t] = 0.f; ssq[t] = 0.f;
    __syncthreads();

    int lane = t & 31;
    int wid = (blockIdx.x * blockDim.x + t) >> 5;
    int nw = (gridDim.x * blockDim.x) >> 5;
    int d0 = lane * 8;

    // packed per-lane constants (4 channel-pairs each)
    ull c0p[4], c1p[4], c2p[4], c3p[4], bbp[4];
    {
        ulonglong2 u;
        u = *(const ulonglong2*)(C + 0 * DD + d0);     c0p[0] = u.x; c0p[1] = u.y;
        u = *(const ulonglong2*)(C + 0 * DD + d0 + 4); c0p[2] = u.x; c0p[3] = u.y;
        u = *(const ulonglong2*)(C + 1 * DD + d0);     c1p[0] = u.x; c1p[1] = u.y;
        u = *(const ulonglong2*)(C + 1 * DD + d0 + 4); c1p[2] = u.x; c1p[3] = u.y;
        u = *(const ulonglong2*)(C + 2 * DD + d0);     c2p[0] = u.x; c2p[1] = u.y;
        u = *(const ulonglong2*)(C + 2 * DD + d0 + 4); c2p[2] = u.x; c2p[3] = u.y;
        u = *(const ulonglong2*)(C + 3 * DD + d0);     c3p[0] = u.x; c3p[1] = u.y;
        u = *(const ulonglong2*)(C + 3 * DD + d0 + 4); c3p[2] = u.x; c3p[3] = u.y;
        u = *(const ulonglong2*)(bc + d0);             bbp[0] = u.x; bbp[1] = u.y;
        u = *(const ulonglong2*)(bc + d0 + 4);         bbp[2] = u.x; bbp[3] = u.y;
    }
    const ull ABS2 = 0x7fffffff7fffffffull;
    const ull D505 = dup2(0.505f);
    const ull D495 = dup2(0.495f);

    float sA[8], qA[8];
#pragma unroll
    for (int i = 0; i < 8; i++) { sA[i] = 0.f; qA[i] = 0.f; }

    for (int n = wid; n < N_NODES; n += nw) {
        int s0 = __ldg(g_start + n);
        int dg = __ldg(g_deg + n);
        ull acc[4] = {0ull, 0ull, 0ull, 0ull};

        int j = 0;
        for (; j + 1 < dg; j += 2) {
            int e0 = __ldg(g_eid + s0 + j);
            int e1 = __ldg(g_eid + s0 + j + 1);
            int sa = __ldg(src + e0);
            int sb = __ldg(src + e1);
            float4 at0 = __ldg((const float4*)ea + e0);
            float4 at1 = __ldg((const float4*)ea + e1);
            const ulonglong2* ha = (const ulonglong2*)(H + (size_t)sa * DD + d0);
            const ulonglong2* hb = (const ulonglong2*)(H + (size_t)sb * DD + d0);
            ulonglong2 pa = ha[0], qa = ha[1];
            ulonglong2 pb = hb[0], qb = hb[1];
            {
                ull ax = dup2(at0.x), ay = dup2(at0.y), az = dup2(at0.z), aw = dup2(at0.w);
                ull hh[4] = {pa.x, pa.y, qa.x, qa.y};
#pragma unroll
                for (int i = 0; i < 4; i++) {
                    ull m = add2(hh[i], bbp[i]);
                    fma2(m, ax, c0p[i]); fma2(m, ay, c1p[i]);
                    fma2(m, az, c2p[i]); fma2(m, aw, c3p[i]);
                    ull ab = m & ABS2;
                    fma2(acc[i], D505, m);
                    fma2(acc[i], D495, ab);
                }
            }
            {
                ull ax = dup2(at1.x), ay = dup2(at1.y), az = dup2(at1.z), aw = dup2(at1.w);
                ull hh[4] = {pb.x, pb.y, qb.x, qb.y};
#pragma unroll
                for (int i = 0; i < 4; i++) {
                    ull m = add2(hh[i], bbp[i]);
                    fma2(m, ax, c0p[i]); fma2(m, ay, c1p[i]);
                    fma2(m, az, c2p[i]); fma2(m, aw, c3p[i]);
                    ull ab = m & ABS2;
                    fma2(acc[i], D505, m);
                    fma2(acc[i], D495, ab);
                }
            }
        }
        if (j < dg) {
            int e0 = __ldg(g_eid + s0 + j);
            int sa = __ldg(src + e0);
            float4 at0 = __ldg((const float4*)ea + e0);
            const ulonglong2* ha = (const ulonglong2*)(H + (size_t)sa * DD + d0);
            ulonglong2 pa = ha[0], qa = ha[1];
            ull ax = dup2(at0.x), ay = dup2(at0.y), az = dup2(at0.z), aw = dup2(at0.w);
            ull hh[4] = {pa.x, pa.y, qa.x, qa.y};
#pragma unroll
            for (int i = 0; i < 4; i++) {
                ull m = add2(hh[i], bbp[i]);
                fma2(m, ax, c0p[i]); fma2(m, ay, c1p[i]);
                fma2(m, az, c2p[i]); fma2(m, aw, c3p[i]);
                ull ab = m & ABS2;
                fma2(acc[i], D505, m);
                fma2(acc[i], D495, ab);
            }
        }

        // store node output (packed pairs == channel layout)
        ulonglong2* op = (ulonglong2*)(agg + (size_t)n * DD + d0);
        op[0] = make_ulonglong2(acc[0], acc[1]);
        op[1] = make_ulonglong2(acc[2], acc[3]);

        // BN stats
#pragma unroll
        for (int i = 0; i < 4; i++) {
            float2 f = up2(acc[i]);
            sA[2 * i]     += f.x;  qA[2 * i]     += f.x * f.x;
            sA[2 * i + 1] += f.y;  qA[2 * i + 1] += f.y * f.y;
        }
    }
#pragma unroll
    for (int i = 0; i < 8; i++) {
        atomicAdd(&ssum[d0 + i], sA[i]);
        atomicAdd(&ssq[d0 + i], qA[i]);
    }
    __syncthreads();
    atomicAdd(&g_bnsum[t], ssum[t]);
    atomicAdd(&g_bnsq[t], ssq[t]);
}

// ---------------- BN scale/shift from stats ----------------------------------
__global__ void bnsc_kernel(const float* __restrict__ w, const float* __restrict__ b)
{
    int c = threadIdx.x;
    const float invN = 1.f / (float)N_NODES;
    float m = g_bnsum[c] * invN;
    float var = g_bnsq[c] * invN - m * m;
    float s = w[c] * rsqrtf(var + EPS);
    g_sc[c] = s;
    g_sh[c] = b[c] - m * s;
}

// ---------------- BN2 apply + leaky (in place) + gate + segment max ----------
__global__ void bn_apply_gate(float* __restrict__ X,
                              const float* __restrict__ gw,
                              const float* __restrict__ gb,
                              const int* __restrict__ batch)
{
    int wid = (blockIdx.x * blockDim.x + threadIdx.x) >> 5;
    int lane = threadIdx.x & 31;
    if (wid >= N_NODES) return;
    int d0 = lane * 8;
    float4* xp = (float4*)(X + (size_t)wid * DD + d0);
    float4 h0 = xp[0], h1 = xp[1];
    float v[8] = {h0.x, h0.y, h0.z, h0.w, h1.x, h1.y, h1.z, h1.w};
    float gsum = 0.f;
#pragma unroll
    for (int i = 0; i < 8; i++) {
        int ch = d0 + i;
        float x = leaky(v[i] * g_sc[ch] + g_sh[ch]);
        v[i] = x;
        gsum += x * __ldg(gw + ch);
    }
    xp[0] = make_float4(v[0], v[1], v[2], v[3]);
    xp[1] = make_float4(v[4], v[5], v[6], v[7]);
#pragma unroll
    for (int off = 16; off; off >>= 1) gsum += __shfl_xor_sync(0xffffffffu, gsum, off);
    if (lane == 0) {
        gsum += __ldg(gb);
        g_gate[wid] = gsum;
        atomicMax(&g_gmax[__ldg(batch + wid)], enc_f(gsum));
    }
}

// ---------------- exp + segment sum ------------------------------------------
__global__ void expsum_kernel(const int* __restrict__ batch)
{
    int n = blockIdx.x * blockDim.x + threadIdx.x;
    if (n >= N_NODES) return;
    int b = __ldg(batch + n);
    float gm = dec_f(g_gmax[b]);
    float e = __expf(g_gate[n] - gm);
    g_e[n] = e;
    atomicAdd(&g_denom[b], e);
}

// ---------------- final weighted aggregation ---------------------------------
__global__ void final_kernel(const float* __restrict__ x2,
                             const int* __restrict__ batch,
                             float* __restrict__ out)
{
    int wid = (blockIdx.x * blockDim.x + threadIdx.x) >> 5;
    int lane = threadIdx.x & 31;
    if (wid >= N_NODES) return;
    int b = __ldg(batch + wid);
    float w = g_e[wid] / g_denom[b];
    int d0 = lane * 8;
    const float4* xp = (const float4*)(x2 + (size_t)wid * DD + d0);
    float4 a0 = __ldg(xp), a1 = __ldg(xp + 1);
    float* op = out + (size_t)b * DD + d0;
    red_add_v4(op,     w * a0.x, w * a0.y, w * a0.z, w * a0.w);
    red_add_v4(op + 4, w * a1.x, w * a1.y, w * a1.z, w * a1.w);
}

// ---------------- launch -----------------------------------------------------
extern "C" void kernel_launch(void* const* d_in, const int* in_sizes, int n_in,
                              void* d_out, int out_size)
{
    const int*   node_ids  = (const int*)d_in[0];
    const int*   edge_index= (const int*)d_in[1];
    const float* edge_attr = (const float*)d_in[2];
    const int*   batch     = (const int*)d_in[3];
    const float* emb       = (const float*)d_in[4];
    const float* c1_lin2_w = (const float*)d_in[5];
    const float* c1_lin2_b = (const float*)d_in[6];
    const float* c1_lin_w  = (const float*)d_in[7];
    const float* c1_lin_b  = (const float*)d_in[8];
    const float* bn1_w     = (const float*)d_in[9];
    const float* bn1_b     = (const float*)d_in[10];
    const float* c2_lin2_w = (const float*)d_in[11];
    const float* c2_lin2_b = (const float*)d_in[12];
    const float* c2_lin_w  = (const float*)d_in[13];
    const float* c2_lin_b  = (const float*)d_in[14];
    const float* bn2_w     = (const float*)d_in[15];
    const float* bn2_b     = (const float*)d_in[16];
    const float* gate_w    = (const float*)d_in[17];
    const float* gate_b    = (const float*)d_in[18];
    float* out = (float*)d_out;

    const int* src = edge_index;
    const int* dst = edge_index + N_EDGES;

    float *pA, *pB, *pC1, *pbc1, *pC2, *pbc2, *psc, *psh;
    cudaGetSymbolAddress((void**)&pA,   g_bufA);
    cudaGetSymbolAddress((void**)&pB,   g_bufB);
    cudaGetSymbolAddress((void**)&pC1,  g_C1);
    cudaGetSymbolAddress((void**)&pbc1, g_bc1);
    cudaGetSymbolAddress((void**)&pC2,  g_C2);
    cudaGetSymbolAddress((void**)&pbc2, g_bc2);
    cudaGetSymbolAddress((void**)&psc,  g_sc);
    cudaGetSymbolAddress((void**)&psh,  g_sh);

    // ---- init ----
    zero_small<<<2, 512>>>();
    zero_deg<<<NSB, 256>>>();
    zero_f<<<(out_size + 255) / 256, 256>>>(out, out_size);

    // ---- CSR build (dst-sorted edge ids) ----
    hist_kernel<<<(N_EDGES + 255) / 256, 256>>>(dst);
    scan1_kernel<<<NSB, 256>>>();
    scan2_kernel<<<1, 256>>>();
    scan3_kernel<<<NSB, 256>>>();
    fill_kernel<<<(N_EDGES + 255) / 256, 256>>>(dst);

    // ---- combined edge matrices ----
    combine_kernel<<<1, 256>>>(c1_lin2_w, c1_lin2_b, c1_lin_w, c1_lin_b,
                               c2_lin2_w, c2_lin2_b, c2_lin_w, c2_lin_b);

    dim3 gg((N_NODES + 127) / 128, DD / 128);

    // ---- layer 1: H1 = emb[node_ids] @ W1^T ----
    gemm_f32x2<<<gg, 256>>>(emb, node_ids, nullptr, nullptr, c1_lin_w, pA, N_NODES, F_IN);

    // ---- conv1 gather -> agg1 (bufB) + bn1 stats ----
    gather_kernel<<<2048, 256>>>(pA, src, edge_attr, pC1, pbc1, pB);
    bnsc_kernel<<<1, 256>>>(bn1_w, bn1_b);

    // ---- layer 2: H2 = leaky(bn1(agg1)) @ W2^T  (BN fused into A-load) ----
    gemm_f32x2<<<gg, 256>>>(pB, nullptr, psc, psh, c2_lin_w, pA, N_NODES, DD);

    // ---- conv2 gather -> agg2 (bufB) + bn2 stats ----
    zero_bn<<<1, 256>>>();
    gather_kernel<<<2048, 256>>>(pA, src, edge_attr, pC2, pbc2, pB);
    bnsc_kernel<<<1, 256>>>(bn2_w, bn2_b);

    // ---- bn2 apply (in place) + gate + segment max ----
    int nb = (N_NODES * 32 + 255) / 256;
    bn_apply_gate<<<nb, 256>>>(pB, gate_w, gate_b, batch);

    // ---- softmax + weighted aggregation ----
    expsum_kernel<<<(N_NODES + 255) / 256, 256>>>(batch);
    final_kernel<<<nb, 256>>>(pB, batch, out);
}

// round 4
// speedup vs baseline: 1.8986x; 1.0540x over previous
#include <cuda_runtime.h>
#include <cstdint>

#define N_NODES  50000
#define N_EDGES  800000
#define N_GRAPHS 512
#define F_IN     128
#define DD       256
#define EPS      1e-5f
#define NEG_SLOPE 0.01f
#define NSB      196          // ceil(N_NODES/256) scan blocks

typedef unsigned long long ull;

// ---------------- scratch (device globals; no allocation allowed) ----------
__device__ float g_bufA[N_NODES * DD];   // H1 -> H2
__device__ float g_bufB[N_NODES * DD];   // agg1 -> agg2 -> x2 (in place)
__device__ float g_C1[4 * DD];
__device__ float g_bc1[DD];
__device__ float g_C2[4 * DD];
__device__ float g_bc2[DD];
__device__ float g_bnsum1[DD];
__device__ float g_bnsq1[DD];
__device__ float g_bnsum2[DD];
__device__ float g_bnsq2[DD];
__device__ float g_sc[DD];
__device__ float g_sh[DD];
__device__ unsigned g_gmax[N_GRAPHS];
__device__ float g_denom[N_GRAPHS];
__device__ float g_gate[N_NODES];
__device__ float g_e[N_NODES];
// CSR
__device__ int g_deg[N_NODES];
__device__ int g_start[N_NODES];
__device__ int g_cursor[N_NODES];
__device__ int g_eid[N_EDGES];
__device__ int g_part[NSB];
__device__ int g_part2[NSB];

// ---------------- helpers ---------------------------------------------------
__device__ __forceinline__ float leaky(float v) {
    return v >= 0.f ? v : NEG_SLOPE * v;
}
__device__ __forceinline__ unsigned enc_f(float x) {
    unsigned u = __float_as_uint(x);
    return (u & 0x80000000u) ? ~u : (u | 0x80000000u);
}
__device__ __forceinline__ float dec_f(unsigned u) {
    return (u & 0x80000000u) ? __uint_as_float(u ^ 0x80000000u) : __uint_as_float(~u);
}
__device__ __forceinline__ void red_add_v4(float* p, float a, float b, float c, float d) {
    asm volatile("red.global.add.v4.f32 [%0], {%1, %2, %3, %4};"
                 :: "l"(p), "f"(a), "f"(b), "f"(c), "f"(d) : "memory");
}
__device__ __forceinline__ ull dup2(float x) {
    ull r; unsigned u = __float_as_uint(x);
    asm("mov.b64 %0, {%1, %1};" : "=l"(r) : "r"(u));
    return r;
}
__device__ __forceinline__ void fma2(ull& d, ull a, ull b) {
    asm("fma.rn.f32x2 %0, %1, %2, %0;" : "+l"(d) : "l"(a), "l"(b));
}
__device__ __forceinline__ ull add2(ull a, ull b) {
    ull r;
    asm("add.rn.f32x2 %0, %1, %2;" : "=l"(r) : "l"(a), "l"(b));
    return r;
}
__device__ __forceinline__ float2 up2(ull v) {
    float2 f; asm("mov.b64 {%0, %1}, %2;" : "=f"(f.x), "=f"(f.y) : "l"(v));
    return f;
}
__device__ __forceinline__ ull pack2(float lo, float hi) {
    ull r;
    asm("mov.b64 %0, {%1, %2};" : "=l"(r) : "f"(lo), "f"(hi));
    return r;
}

// ---------------- zero / init kernels ---------------------------------------
__global__ void zero_f(float* p, int n) {
    int i = blockIdx.x * blockDim.x + threadIdx.x;
    int stride = gridDim.x * blockDim.x;
    for (; i < n; i += stride) p[i] = 0.f;
}
__global__ void zero_small() {
    int t = blockIdx.x * blockDim.x + threadIdx.x;
    if (t < DD) {
        g_bnsum1[t] = 0.f; g_bnsq1[t] = 0.f;
        g_bnsum2[t] = 0.f; g_bnsq2[t] = 0.f;
    }
    if (t < N_GRAPHS) { g_gmax[t] = 0u; g_denom[t] = 0.f; }
}
__global__ void zero_deg() {
    int i = blockIdx.x * blockDim.x + threadIdx.x;
    if (i < N_NODES) g_deg[i] = 0;
}

// ---------------- CSR build --------------------------------------------------
__global__ void hist_kernel(const int* __restrict__ dst) {
    int e = blockIdx.x * blockDim.x + threadIdx.x;
    if (e < N_EDGES) atomicAdd(&g_deg[__ldg(dst + e)], 1);
}
__global__ void scan1_kernel() {
    __shared__ int sh[256];
    int i = blockIdx.x * 256 + threadIdx.x;
    int v = (i < N_NODES) ? g_deg[i] : 0;
    sh[threadIdx.x] = v; __syncthreads();
#pragma unroll
    for (int off = 1; off < 256; off <<= 1) {
        int tv = (threadIdx.x >= off) ? sh[threadIdx.x - off] : 0;
        __syncthreads();
        sh[threadIdx.x] += tv;
        __syncthreads();
    }
    if (i < N_NODES) g_start[i] = sh[threadIdx.x] - v;   // block-local exclusive
    if (threadIdx.x == 255) g_part[blockIdx.x] = sh[255];
}
__global__ void scan2_kernel() {
    __shared__ int sh[256];
    int t = threadIdx.x;
    int v = (t < NSB) ? g_part[t] : 0;
    sh[t] = v; __syncthreads();
#pragma unroll
    for (int off = 1; off < 256; off <<= 1) {
        int tv = (t >= off) ? sh[t - off] : 0;
        __syncthreads();
        sh[t] += tv;
        __syncthreads();
    }
    if (t < NSB) g_part2[t] = sh[t] - v;                 // exclusive
}
__global__ void scan3_kernel() {
    int i = blockIdx.x * 256 + threadIdx.x;
    if (i < N_NODES) {
        int s = g_start[i] + g_part2[blockIdx.x];
        g_start[i] = s;
        g_cursor[i] = s;
    }
}
__global__ void fill_kernel(const int* __restrict__ dst) {
    int e = blockIdx.x * blockDim.x + threadIdx.x;
    if (e < N_EDGES) {
        int d = __ldg(dst + e);
        int p = atomicAdd(&g_cursor[d], 1);
        g_eid[p] = e;
    }
}

// ---------------- combined edge matrices ------------------------------------
__global__ void combine_kernel(
    const float* __restrict__ l2w1, const float* __restrict__ l2b1,
    const float* __restrict__ lw1,  const float* __restrict__ lb1,
    const float* __restrict__ l2w2, const float* __restrict__ l2b2,
    const float* __restrict__ lw2,  const float* __restrict__ lb2)
{
    int d = threadIdx.x;   // 256 threads
    {
        float a0 = 0.f, a1 = 0.f, a2 = 0.f, a3 = 0.f, bb = 0.f;
        for (int f = 0; f < F_IN; f++) {
            float w = lw1[d * F_IN + f];
            float4 l2 = *(const float4*)(l2w1 + f * 4);
            a0 += l2.x * w; a1 += l2.y * w; a2 += l2.z * w; a3 += l2.w * w;
            bb += l2b1[f] * w;
        }
        g_C1[0 * DD + d] = a0; g_C1[1 * DD + d] = a1;
        g_C1[2 * DD + d] = a2; g_C1[3 * DD + d] = a3;
        g_bc1[d] = bb + lb1[d];
    }
    {
        float a0 = 0.f, a1 = 0.f, a2 = 0.f, a3 = 0.f, bb = 0.f;
        for (int f = 0; f < DD; f++) {
            float w = lw2[d * DD + f];
            float4 l2 = *(const float4*)(l2w2 + f * 4);
            a0 += l2.x * w; a1 += l2.y * w; a2 += l2.z * w; a3 += l2.w * w;
            bb += l2b2[f] * w;
        }
        g_C2[0 * DD + d] = a0; g_C2[1 * DD + d] = a1;
        g_C2[2 * DD + d] = a2; g_C2[3 * DD + d] = a3;
        g_bc2[d] = bb + lb2[d];
    }
}

// ---------------- GEMM v3 (f32x2, conflict-free smem, reg double buffer) ----
// out[m][n] = sum_k A'[m][k] * W[n][k];  A' = leaky(A*sc + sh) if sc != null.
// Tile 128x128, BK=16, 256 threads, 8x8 micro-tile.
// As: plain floats (dup to pairs via register movs).
// Bs: [kk][i][tx*4+c] layout (n = tx*8 + i*4 + c) -> conflict-free LDS.128.
__global__ void __launch_bounds__(256, 2)
gemm_v3(const float* __restrict__ A, const int* __restrict__ idx,
        const float* __restrict__ sc, const float* __restrict__ sh,
        const float* __restrict__ W, float* __restrict__ out,
        int M, int K)
{
    __shared__ float As[16][128];      // 8 KB
    __shared__ float Bs[16][2][64];    // 8 KB
    int t = threadIdx.x;
    int bm = blockIdx.x * 128;
    int bn = blockIdx.y * 128;
    int tx = t & 15, ty = t >> 4;
    int lr = t >> 1;            // 0..127 (A row, and B n-index)
    int lk = (t & 1) * 8;       // 0 or 8

    // B store mapping for n = lr:  Bs[kk][ib][txb*4+cb]
    int ib  = (lr >> 2) & 1;
    int txb = lr >> 3;
    int cb  = lr & 3;

    ull acc[8][4];
#pragma unroll
    for (int i = 0; i < 8; i++)
#pragma unroll
        for (int j = 0; j < 4; j++) acc[i][j] = 0ull;

    int m0 = bm + lr;
    int mc = m0 < M ? m0 : (M - 1);
    int arow = idx ? __ldg(idx + mc) : mc;
    const float* Arow = A + (size_t)arow * K;
    const float* Wrow = W + (size_t)(bn + lr) * K;

    float4 a0, a1, w0, w1;

    // ---- prologue: load tile 0 ----
    {
        a0 = __ldg((const float4*)(Arow + lk));
        a1 = __ldg((const float4*)(Arow + lk + 4));
        w0 = __ldg((const float4*)(Wrow + lk));
        w1 = __ldg((const float4*)(Wrow + lk + 4));
        if (sc) {
            float4 s0 = __ldg((const float4*)(sc + lk));
            float4 s1 = __ldg((const float4*)(sc + lk + 4));
            float4 h0 = __ldg((const float4*)(sh + lk));
            float4 h1 = __ldg((const float4*)(sh + lk + 4));
            a0.x = leaky(a0.x * s0.x + h0.x); a0.y = leaky(a0.y * s0.y + h0.y);
            a0.z = leaky(a0.z * s0.z + h0.z); a0.w = leaky(a0.w * s0.w + h0.w);
            a1.x = leaky(a1.x * s1.x + h1.x); a1.y = leaky(a1.y * s1.y + h1.y);
            a1.z = leaky(a1.z * s1.z + h1.z); a1.w = leaky(a1.w * s1.w + h1.w);
        }
        As[lk + 0][lr] = a0.x; As[lk + 1][lr] = a0.y;
        As[lk + 2][lr] = a0.z; As[lk + 3][lr] = a0.w;
        As[lk + 4][lr] = a1.x; As[lk + 5][lr] = a1.y;
        As[lk + 6][lr] = a1.z; As[lk + 7][lr] = a1.w;
        Bs[lk + 0][ib][txb * 4 + cb] = w0.x; Bs[lk + 1][ib][txb * 4 + cb] = w0.y;
        Bs[lk + 2][ib][txb * 4 + cb] = w0.z; Bs[lk + 3][ib][txb * 4 + cb] = w0.w;
        Bs[lk + 4][ib][txb * 4 + cb] = w1.x; Bs[lk + 5][ib][txb * 4 + cb] = w1.y;
        Bs[lk + 6][ib][txb * 4 + cb] = w1.z; Bs[lk + 7][ib][txb * 4 + cb] = w1.w;
    }
    __syncthreads();

    for (int k0 = 0; k0 < K; k0 += 16) {
        bool more = (k0 + 16) < K;
        if (more) {
            int kn = k0 + 16;
            a0 = __ldg((const float4*)(Arow + kn + lk));
            a1 = __ldg((const float4*)(Arow + kn + lk + 4));
            w0 = __ldg((const float4*)(Wrow + kn + lk));
            w1 = __ldg((const float4*)(Wrow + kn + lk + 4));
            if (sc) {
                float4 s0 = __ldg((const float4*)(sc + kn + lk));
                float4 s1 = __ldg((const float4*)(sc + kn + lk + 4));
                float4 h0 = __ldg((const float4*)(sh + kn + lk));
                float4 h1 = __ldg((const float4*)(sh + kn + lk + 4));
                a0.x = leaky(a0.x * s0.x + h0.x); a0.y = leaky(a0.y * s0.y + h0.y);
                a0.z = leaky(a0.z * s0.z + h0.z); a0.w = leaky(a0.w * s0.w + h0.w);
                a1.x = leaky(a1.x * s1.x + h1.x); a1.y = leaky(a1.y * s1.y + h1.y);
                a1.z = leaky(a1.z * s1.z + h1.z); a1.w = leaky(a1.w * s1.w + h1.w);
            }
        }
#pragma unroll
        for (int kk = 0; kk < 16; kk++) {
            float4 avL = *(const float4*)&As[kk][ty * 8 + 0];
            float4 avH = *(const float4*)&As[kk][ty * 8 + 4];
            float4 b0 = *(const float4*)&Bs[kk][0][tx * 4];
            float4 b1 = *(const float4*)&Bs[kk][1][tx * 4];
            ull ad[8];
            ad[0] = dup2(avL.x); ad[1] = dup2(avL.y);
            ad[2] = dup2(avL.z); ad[3] = dup2(avL.w);
            ad[4] = dup2(avH.x); ad[5] = dup2(avH.y);
            ad[6] = dup2(avH.z); ad[7] = dup2(avH.w);
            ull bp[4];
            bp[0] = pack2(b0.x, b0.y); bp[1] = pack2(b0.z, b0.w);
            bp[2] = pack2(b1.x, b1.y); bp[3] = pack2(b1.z, b1.w);
#pragma unroll
            for (int i = 0; i < 8; i++)
#pragma unroll
                for (int j = 0; j < 4; j++) fma2(acc[i][j], ad[i], bp[j]);
        }
        if (more) {
            __syncthreads();
            As[lk + 0][lr] = a0.x; As[lk + 1][lr] = a0.y;
            As[lk + 2][lr] = a0.z; As[lk + 3][lr] = a0.w;
            As[lk + 4][lr] = a1.x; As[lk + 5][lr] = a1.y;
            As[lk + 6][lr] = a1.z; As[lk + 7][lr] = a1.w;
            Bs[lk + 0][ib][txb * 4 + cb] = w0.x; Bs[lk + 1][ib][txb * 4 + cb] = w0.y;
            Bs[lk + 2][ib][txb * 4 + cb] = w0.z; Bs[lk + 3][ib][txb * 4 + cb] = w0.w;
            Bs[lk + 4][ib][txb * 4 + cb] = w1.x; Bs[lk + 5][ib][txb * 4 + cb] = w1.y;
            Bs[lk + 6][ib][txb * 4 + cb] = w1.z; Bs[lk + 7][ib][txb * 4 + cb] = w1.w;
            __syncthreads();
        }
    }
#pragma unroll
    for (int i = 0; i < 8; i++) {
        int m = bm + ty * 8 + i;
        if (m < M) {
            float2 r0 = up2(acc[i][0]), r1 = up2(acc[i][1]);
            float2 r2 = up2(acc[i][2]), r3 = up2(acc[i][3]);
            float* op = out + (size_t)m * DD + bn + tx * 8;
            *(float4*)(op)     = make_float4(r0.x, r0.y, r1.x, r1.y);
            *(float4*)(op + 4) = make_float4(r2.x, r2.y, r3.x, r3.y);
        }
    }
}

// ---------------- per-edge packed accumulate helper --------------------------
__device__ __forceinline__ void edge_accum(
    ull acc[4], float4 at, ulonglong2 p, ulonglong2 q,
    const ull c0p[4], const ull c1p[4], const ull c2p[4], const ull c3p[4],
    const ull bbp[4])
{
    const ull ABS2 = 0x7fffffff7fffffffull;
    const ull D505 = 0x3f0147ae3f0147aeull;  // dup2(0.505f)
    const ull D495 = 0x3efd70a43efd70a4ull;  // dup2(0.495f)
    ull ax = dup2(at.x), ay = dup2(at.y), az = dup2(at.z), aw = dup2(at.w);
    ull hh[4] = {p.x, p.y, q.x, q.y};
#pragma unroll
    for (int i = 0; i < 4; i++) {
        ull m = add2(hh[i], bbp[i]);
        fma2(m, ax, c0p[i]); fma2(m, ay, c1p[i]);
        fma2(m, az, c2p[i]); fma2(m, aw, c3p[i]);
        ull ab = m & ABS2;
        fma2(acc[i], D505, m);
        fma2(acc[i], D495, ab);
    }
}

// ---------------- CSR gather (packed f32x2, unroll-4) ------------------------
__global__ void gather_kernel(const float* __restrict__ H,
                              const int* __restrict__ src,
                              const float* __restrict__ ea,
                              const float* __restrict__ C,
                              const float* __restrict__ bc,
                              float* __restrict__ agg,
                              float* __restrict__ bnsum,
                              float* __restrict__ bnsq)
{
    __shared__ float ssum[DD];
    __shared__ float ssq[DD];
    int t = threadIdx.x;
    ssum[t] = 0.f; ssq[t] = 0.f;
    __syncthreads();

    int lane = t & 31;
    int wid = (blockIdx.x * blockDim.x + t) >> 5;
    int nw = (gridDim.x * blockDim.x) >> 5;
    int d0 = lane * 8;

    ull c0p[4], c1p[4], c2p[4], c3p[4], bbp[4];
    {
        ulonglong2 u;
        u = *(const ulonglong2*)(C + 0 * DD + d0);     c0p[0] = u.x; c0p[1] = u.y;
        u = *(const ulonglong2*)(C + 0 * DD + d0 + 4); c0p[2] = u.x; c0p[3] = u.y;
        u = *(const ulonglong2*)(C + 1 * DD + d0);     c1p[0] = u.x; c1p[1] = u.y;
        u = *(const ulonglong2*)(C + 1 * DD + d0 + 4); c1p[2] = u.x; c1p[3] = u.y;
        u = *(const ulonglong2*)(C + 2 * DD + d0);     c2p[0] = u.x; c2p[1] = u.y;
        u = *(const ulonglong2*)(C + 2 * DD + d0 + 4); c2p[2] = u.x; c2p[3] = u.y;
        u = *(const ulonglong2*)(C + 3 * DD + d0);     c3p[0] = u.x; c3p[1] = u.y;
        u = *(const ulonglong2*)(C + 3 * DD + d0 + 4); c3p[2] = u.x; c3p[3] = u.y;
        u = *(const ulonglong2*)(bc + d0);             bbp[0] = u.x; bbp[1] = u.y;
        u = *(const ulonglong2*)(bc + d0 + 4);         bbp[2] = u.x; bbp[3] = u.y;
    }

    float sA[8], qA[8];
#pragma unroll
    for (int i = 0; i < 8; i++) { sA[i] = 0.f; qA[i] = 0.f; }

    for (int n = wid; n < N_NODES; n += nw) {
        int s0 = __ldg(g_start + n);
        int dg = __ldg(g_deg + n);
        ull acc[4] = {0ull, 0ull, 0ull, 0ull};

        int j = 0;
        for (; j + 3 < dg; j += 4) {
            int e0 = __ldg(g_eid + s0 + j);
            int e1 = __ldg(g_eid + s0 + j + 1);
            int e2 = __ldg(g_eid + s0 + j + 2);
            int e3 = __ldg(g_eid + s0 + j + 3);
            int sa = __ldg(src + e0);
            int sb = __ldg(src + e1);
            int sc2 = __ldg(src + e2);
            int sd = __ldg(src + e3);
            float4 at0 = __ldg((const float4*)ea + e0);
            float4 at1 = __ldg((const float4*)ea + e1);
            float4 at2 = __ldg((const float4*)ea + e2);
            float4 at3 = __ldg((const float4*)ea + e3);
            const ulonglong2* ha = (const ulonglong2*)(H + (size_t)sa * DD + d0);
            const ulonglong2* hb = (const ulonglong2*)(H + (size_t)sb * DD + d0);
            const ulonglong2* hc = (const ulonglong2*)(H + (size_t)sc2 * DD + d0);
            const ulonglong2* hd = (const ulonglong2*)(H + (size_t)sd * DD + d0);
            ulonglong2 pa = ha[0], qa = ha[1];
            ulonglong2 pb = hb[0], qb = hb[1];
            ulonglong2 pc = hc[0], qc = hc[1];
            ulonglong2 pd = hd[0], qd = hd[1];
            edge_accum(acc, at0, pa, qa, c0p, c1p, c2p, c3p, bbp);
            edge_accum(acc, at1, pb, qb, c0p, c1p, c2p, c3p, bbp);
            edge_accum(acc, at2, pc, qc, c0p, c1p, c2p, c3p, bbp);
            edge_accum(acc, at3, pd, qd, c0p, c1p, c2p, c3p, bbp);
        }
        for (; j < dg; j++) {
            int e0 = __ldg(g_eid + s0 + j);
            int sa = __ldg(src + e0);
            float4 at0 = __ldg((const float4*)ea + e0);
            const ulonglong2* ha = (const ulonglong2*)(H + (size_t)sa * DD + d0);
            ulonglong2 pa = ha[0], qa = ha[1];
            edge_accum(acc, at0, pa, qa, c0p, c1p, c2p, c3p, bbp);
        }

        ulonglong2* op = (ulonglong2*)(agg + (size_t)n * DD + d0);
        op[0] = make_ulonglong2(acc[0], acc[1]);
        op[1] = make_ulonglong2(acc[2], acc[3]);

#pragma unroll
        for (int i = 0; i < 4; i++) {
            float2 f = up2(acc[i]);
            sA[2 * i]     += f.x;  qA[2 * i]     += f.x * f.x;
            sA[2 * i + 1] += f.y;  qA[2 * i + 1] += f.y * f.y;
        }
    }
#pragma unroll
    for (int i = 0; i < 8; i++) {
        atomicAdd(&ssum[d0 + i], sA[i]);
        atomicAdd(&ssq[d0 + i], qA[i]);
    }
    __syncthreads();
    atomicAdd(&bnsum[t], ssum[t]);
    atomicAdd(&bnsq[t], ssq[t]);
}

// ---------------- BN scale/shift from stats ----------------------------------
__global__ void bnsc_kernel(const float* __restrict__ w, const float* __restrict__ b,
                            const float* __restrict__ bnsum, const float* __restrict__ bnsq)
{
    int c = threadIdx.x;
    const float invN = 1.f / (float)N_NODES;
    float m = bnsum[c] * invN;
    float var = bnsq[c] * invN - m * m;
    float s = w[c] * rsqrtf(var + EPS);
    g_sc[c] = s;
    g_sh[c] = b[c] - m * s;
}

// ---------------- BN2 apply + leaky (in place) + gate + segment max ----------
__global__ void bn_apply_gate(float* __restrict__ X,
                              const float* __restrict__ gw,
                              const float* __restrict__ gb,
                              const int* __restrict__ batch)
{
    int wid = (blockIdx.x * blockDim.x + threadIdx.x) >> 5;
    int lane = threadIdx.x & 31;
    if (wid >= N_NODES) return;
    int d0 = lane * 8;
    float4* xp = (float4*)(X + (size_t)wid * DD + d0);
    float4 h0 = xp[0], h1 = xp[1];
    float v[8] = {h0.x, h0.y, h0.z, h0.w, h1.x, h1.y, h1.z, h1.w};
    float gsum = 0.f;
#pragma unroll
    for (int i = 0; i < 8; i++) {
        int ch = d0 + i;
        float x = leaky(v[i] * g_sc[ch] + g_sh[ch]);
        v[i] = x;
        gsum += x * __ldg(gw + ch);
    }
    xp[0] = make_float4(v[0], v[1], v[2], v[3]);
    xp[1] = make_float4(v[4], v[5], v[6], v[7]);
#pragma unroll
    for (int off = 16; off; off >>= 1) gsum += __shfl_xor_sync(0xffffffffu, gsum, off);
    if (lane == 0) {
        gsum += __ldg(gb);
        g_gate[wid] = gsum;
        atomicMax(&g_gmax[__ldg(batch + wid)], enc_f(gsum));
    }
}

// ---------------- exp + segment sum ------------------------------------------
__global__ void expsum_kernel(const int* __restrict__ batch)
{
    int n = blockIdx.x * blockDim.x + threadIdx.x;
    if (n >= N_NODES) return;
    int b = __ldg(batch + n);
    float gm = dec_f(g_gmax[b]);
    float e = __expf(g_gate[n] - gm);
    g_e[n] = e;
    atomicAdd(&g_denom[b], e);
}

// ---------------- final weighted aggregation ---------------------------------
__global__ void final_kernel(const float* __restrict__ x2,
                             const int* __restrict__ batch,
                             float* __restrict__ out)
{
    int wid = (blockIdx.x * blockDim.x + threadIdx.x) >> 5;
    int lane = threadIdx.x & 31;
    if (wid >= N_NODES) return;
    int b = __ldg(batch + wid);
    float w = g_e[wid] / g_denom[b];
    int d0 = lane * 8;
    const float4* xp = (const float4*)(x2 + (size_t)wid * DD + d0);
    float4 a0 = __ldg(xp), a1 = __ldg(xp + 1);
    float* op = out + (size_t)b * DD + d0;
    red_add_v4(op,     w * a0.x, w * a0.y, w * a0.z, w * a0.w);
    red_add_v4(op + 4, w * a1.x, w * a1.y, w * a1.z, w * a1.w);
}

// ---------------- launch -----------------------------------------------------
extern "C" void kernel_launch(void* const* d_in, const int* in_sizes, int n_in,
                              void* d_out, int out_size)
{
    const int*   node_ids  = (const int*)d_in[0];
    const int*   edge_index= (const int*)d_in[1];
    const float* edge_attr = (const float*)d_in[2];
    const int*   batch     = (const int*)d_in[3];
    const float* emb       = (const float*)d_in[4];
    const float* c1_lin2_w = (const float*)d_in[5];
    const float* c1_lin2_b = (const float*)d_in[6];
    const float* c1_lin_w  = (const float*)d_in[7];
    const float* c1_lin_b  = (const float*)d_in[8];
    const float* bn1_w     = (const float*)d_in[9];
    const float* bn1_b     = (const float*)d_in[10];
    const float* c2_lin2_w = (const float*)d_in[11];
    const float* c2_lin2_b = (const float*)d_in[12];
    const float* c2_lin_w  = (const float*)d_in[13];
    const float* c2_lin_b  = (const float*)d_in[14];
    const float* bn2_w     = (const float*)d_in[15];
    const float* bn2_b     = (const float*)d_in[16];
    const float* gate_w    = (const float*)d_in[17];
    const float* gate_b    = (const float*)d_in[18];
    float* out = (float*)d_out;

    const int* src = edge_index;
    const int* dst = edge_index + N_EDGES;

    float *pA, *pB, *pC1, *pbc1, *pC2, *pbc2, *psc, *psh;
    float *pbs1, *pbq1, *pbs2, *pbq2;
    cudaGetSymbolAddress((void**)&pA,   g_bufA);
    cudaGetSymbolAddress((void**)&pB,   g_bufB);
    cudaGetSymbolAddress((void**)&pC1,  g_C1);
    cudaGetSymbolAddress((void**)&pbc1, g_bc1);
    cudaGetSymbolAddress((void**)&pC2,  g_C2);
    cudaGetSymbolAddress((void**)&pbc2, g_bc2);
    cudaGetSymbolAddress((void**)&psc,  g_sc);
    cudaGetSymbolAddress((void**)&psh,  g_sh);
    cudaGetSymbolAddress((void**)&pbs1, g_bnsum1);
    cudaGetSymbolAddress((void**)&pbq1, g_bnsq1);
    cudaGetSymbolAddress((void**)&pbs2, g_bnsum2);
    cudaGetSymbolAddress((void**)&pbq2, g_bnsq2);

    // ---- init ----
    zero_small<<<2, 512>>>();
    zero_deg<<<NSB, 256>>>();
    zero_f<<<(out_size + 255) / 256, 256>>>(out, out_size);

    // ---- CSR build (dst-sorted edge ids) ----
    hist_kernel<<<(N_EDGES + 255) / 256, 256>>>(dst);
    scan1_kernel<<<NSB, 256>>>();
    scan2_kernel<<<1, 256>>>();
    scan3_kernel<<<NSB, 256>>>();
    fill_kernel<<<(N_EDGES + 255) / 256, 256>>>(dst);

    // ---- combined edge matrices ----
    combine_kernel<<<1, 256>>>(c1_lin2_w, c1_lin2_b, c1_lin_w, c1_lin_b,
                               c2_lin2_w, c2_lin2_b, c2_lin_w, c2_lin_b);

    dim3 gg((N_NODES + 127) / 128, DD / 128);

    // ---- layer 1: H1 = emb[node_ids] @ W1^T ----
    gemm_v3<<<gg, 256>>>(emb, node_ids, nullptr, nullptr, c1_lin_w, pA, N_NODES, F_IN);

    // ---- conv1 gather -> agg1 (bufB) + bn1 stats ----
    gather_kernel<<<2048, 256>>>(pA, src, edge_attr, pC1, pbc1, pB, pbs1, pbq1);
    bnsc_kernel<<<1, 256>>>(bn1_w, bn1_b, pbs1, pbq1);

    // ---- layer 2: H2 = leaky(bn1(agg1)) @ W2^T  (BN fused into A-load) ----
    gemm_v3<<<gg, 256>>>(pB, nullptr, psc, psh, c2_lin_w, pA, N_NODES, DD);

    // ---- conv2 gather -> agg2 (bufB) + bn2 stats ----
    gather_kernel<<<2048, 256>>>(pA, src, edge_attr, pC2, pbc2, pB, pbs2, pbq2);
    bnsc_kernel<<<1, 256>>>(bn2_w, bn2_b, pbs2, pbq2);

    // ---- bn2 apply (in place) + gate + segment max ----
    int nb = (N_NODES * 32 + 255) / 256;
    bn_apply_gate<<<nb, 256>>>(pB, gate_w, gate_b, batch);

    // ---- softmax + weighted aggregation ----
    expsum_kernel<<<(N_NODES + 255) / 256, 256>>>(batch);
    final_kernel<<<nb, 256>>>(pB, batch, out);
}

// round 5
// speedup vs baseline: 2.0960x; 1.1040x over previous
#include <cuda_runtime.h>
#include <cstdint>

#define N_NODES  50000
#define N_EDGES  800000
#define N_GRAPHS 512
#define F_IN     128
#define DD       256
#define EPS      1e-5f
#define NEG_SLOPE 0.01f
#define NSB      196          // ceil(N_NODES/256) scan blocks

typedef unsigned long long ull;

// ---------------- scratch (device globals; no allocation allowed) ----------
__device__ float g_bufA[N_NODES * DD];   // H1 -> H2
__device__ float g_bufB[N_NODES * DD];   // agg1 -> agg2 -> x2 (in place)
__device__ float g_C1[4 * DD];
__device__ float g_bc1[DD];
__device__ float g_C2[4 * DD];
__device__ float g_bc2[DD];
__device__ float g_bnsum1[DD];
__device__ float g_bnsq1[DD];
__device__ float g_bnsum2[DD];
__device__ float g_bnsq2[DD];
__device__ float g_sc[DD];
__device__ float g_sh[DD];
__device__ unsigned g_gmax[N_GRAPHS];
__device__ float g_denom[N_GRAPHS];
__device__ float g_gate[N_NODES];
__device__ float g_e[N_NODES];
// CSR (dst-sorted, with permuted src and edge_attr)
__device__ int    g_deg[N_NODES];
__device__ int    g_start[N_NODES];
__device__ int    g_cursor[N_NODES];
__device__ int    g_srcs[N_EDGES];
__device__ float4 g_eas[N_EDGES];
__device__ int    g_part[NSB];
__device__ int    g_part2[NSB];

// ---------------- helpers ---------------------------------------------------
__device__ __forceinline__ float leaky(float v) {
    return v >= 0.f ? v : NEG_SLOPE * v;
}
__device__ __forceinline__ unsigned enc_f(float x) {
    unsigned u = __float_as_uint(x);
    return (u & 0x80000000u) ? ~u : (u | 0x80000000u);
}
__device__ __forceinline__ float dec_f(unsigned u) {
    return (u & 0x80000000u) ? __uint_as_float(u ^ 0x80000000u) : __uint_as_float(~u);
}
__device__ __forceinline__ void red_add_v4(float* p, float a, float b, float c, float d) {
    asm volatile("red.global.add.v4.f32 [%0], {%1, %2, %3, %4};"
                 :: "l"(p), "f"(a), "f"(b), "f"(c), "f"(d) : "memory");
}
__device__ __forceinline__ ull dup2(float x) {
    ull r; unsigned u = __float_as_uint(x);
    asm("mov.b64 %0, {%1, %1};" : "=l"(r) : "r"(u));
    return r;
}
__device__ __forceinline__ void fma2(ull& d, ull a, ull b) {
    asm("fma.rn.f32x2 %0, %1, %2, %0;" : "+l"(d) : "l"(a), "l"(b));
}
__device__ __forceinline__ ull add2(ull a, ull b) {
    ull r;
    asm("add.rn.f32x2 %0, %1, %2;" : "=l"(r) : "l"(a), "l"(b));
    return r;
}
__device__ __forceinline__ float2 up2(ull v) {
    float2 f; asm("mov.b64 {%0, %1}, %2;" : "=f"(f.x), "=f"(f.y) : "l"(v));
    return f;
}
__device__ __forceinline__ ull pack2(float lo, float hi) {
    ull r;
    asm("mov.b64 %0, {%1, %2};" : "=l"(r) : "f"(lo), "f"(hi));
    return r;
}

// ---------------- zero / init kernels ---------------------------------------
__global__ void zero_f(float* p, int n) {
    int i = blockIdx.x * blockDim.x + threadIdx.x;
    int stride = gridDim.x * blockDim.x;
    for (; i < n; i += stride) p[i] = 0.f;
}
// one kernel: deg + bn stats + graph-level accumulators
__global__ void zero_init() {
    int i = blockIdx.x * blockDim.x + threadIdx.x;
    if (i < N_NODES) g_deg[i] = 0;
    if (i < DD) {
        g_bnsum1[i] = 0.f; g_bnsq1[i] = 0.f;
        g_bnsum2[i] = 0.f; g_bnsq2[i] = 0.f;
    }
    if (i < N_GRAPHS) { g_gmax[i] = 0u; g_denom[i] = 0.f; }
}

// ---------------- CSR build --------------------------------------------------
__global__ void hist_kernel(const int* __restrict__ dst) {
    int e = blockIdx.x * blockDim.x + threadIdx.x;
    if (e < N_EDGES) atomicAdd(&g_deg[__ldg(dst + e)], 1);
}
__global__ void scan1_kernel() {
    __shared__ int sh[256];
    int i = blockIdx.x * 256 + threadIdx.x;
    int v = (i < N_NODES) ? g_deg[i] : 0;
    sh[threadIdx.x] = v; __syncthreads();
#pragma unroll
    for (int off = 1; off < 256; off <<= 1) {
        int tv = (threadIdx.x >= off) ? sh[threadIdx.x - off] : 0;
        __syncthreads();
        sh[threadIdx.x] += tv;
        __syncthreads();
    }
    if (i < N_NODES) g_start[i] = sh[threadIdx.x] - v;   // block-local exclusive
    if (threadIdx.x == 255) g_part[blockIdx.x] = sh[255];
}
__global__ void scan2_kernel() {
    __shared__ int sh[256];
    int t = threadIdx.x;
    int v = (t < NSB) ? g_part[t] : 0;
    sh[t] = v; __syncthreads();
#pragma unroll
    for (int off = 1; off < 256; off <<= 1) {
        int tv = (t >= off) ? sh[t - off] : 0;
        __syncthreads();
        sh[t] += tv;
        __syncthreads();
    }
    if (t < NSB) g_part2[t] = sh[t] - v;                 // exclusive
}
__global__ void scan3_kernel() {
    int i = blockIdx.x * 256 + threadIdx.x;
    if (i < N_NODES) {
        int s = g_start[i] + g_part2[blockIdx.x];
        g_start[i] = s;
        g_cursor[i] = s;
    }
}
// permute src and edge_attr into dst-sorted order
__global__ void fill_kernel(const int* __restrict__ src,
                            const int* __restrict__ dst,
                            const float* __restrict__ ea) {
    int e = blockIdx.x * blockDim.x + threadIdx.x;
    if (e < N_EDGES) {
        int d = __ldg(dst + e);
        int p = atomicAdd(&g_cursor[d], 1);
        g_srcs[p] = __ldg(src + e);
        g_eas[p] = __ldg((const float4*)ea + e);
    }
}

// ---------------- combined edge matrices ------------------------------------
__global__ void combine_kernel(
    const float* __restrict__ l2w1, const float* __restrict__ l2b1,
    const float* __restrict__ lw1,  const float* __restrict__ lb1,
    const float* __restrict__ l2w2, const float* __restrict__ l2b2,
    const float* __restrict__ lw2,  const float* __restrict__ lb2)
{
    int d = threadIdx.x;   // 256 threads
    {
        float a0 = 0.f, a1 = 0.f, a2 = 0.f, a3 = 0.f, bb = 0.f;
        for (int f = 0; f < F_IN; f++) {
            float w = lw1[d * F_IN + f];
            float4 l2 = *(const float4*)(l2w1 + f * 4);
            a0 += l2.x * w; a1 += l2.y * w; a2 += l2.z * w; a3 += l2.w * w;
            bb += l2b1[f] * w;
        }
        g_C1[0 * DD + d] = a0; g_C1[1 * DD + d] = a1;
        g_C1[2 * DD + d] = a2; g_C1[3 * DD + d] = a3;
        g_bc1[d] = bb + lb1[d];
    }
    {
        float a0 = 0.f, a1 = 0.f, a2 = 0.f, a3 = 0.f, bb = 0.f;
        for (int f = 0; f < DD; f++) {
            float w = lw2[d * DD + f];
            float4 l2 = *(const float4*)(l2w2 + f * 4);
            a0 += l2.x * w; a1 += l2.y * w; a2 += l2.z * w; a3 += l2.w * w;
            bb += l2b2[f] * w;
        }
        g_C2[0 * DD + d] = a0; g_C2[1 * DD + d] = a1;
        g_C2[2 * DD + d] = a2; g_C2[3 * DD + d] = a3;
        g_bc2[d] = bb + lb2[d];
    }
}

// ---------------- GEMM v3 (f32x2, conflict-free smem, reg double buffer) ----
__global__ void __launch_bounds__(256, 2)
gemm_v3(const float* __restrict__ A, const int* __restrict__ idx,
        const float* __restrict__ sc, const float* __restrict__ sh,
        const float* __restrict__ W, float* __restrict__ out,
        int M, int K)
{
    __shared__ float As[16][128];      // 8 KB
    __shared__ float Bs[16][2][64];    // 8 KB
    int t = threadIdx.x;
    int bm = blockIdx.x * 128;
    int bn = blockIdx.y * 128;
    int tx = t & 15, ty = t >> 4;
    int lr = t >> 1;            // 0..127 (A row, and B n-index)
    int lk = (t & 1) * 8;       // 0 or 8

    int ib  = (lr >> 2) & 1;
    int txb = lr >> 3;
    int cb  = lr & 3;

    ull acc[8][4];
#pragma unroll
    for (int i = 0; i < 8; i++)
#pragma unroll
        for (int j = 0; j < 4; j++) acc[i][j] = 0ull;

    int m0 = bm + lr;
    int mc = m0 < M ? m0 : (M - 1);
    int arow = idx ? __ldg(idx + mc) : mc;
    const float* Arow = A + (size_t)arow * K;
    const float* Wrow = W + (size_t)(bn + lr) * K;

    float4 a0, a1, w0, w1;

    {
        a0 = __ldg((const float4*)(Arow + lk));
        a1 = __ldg((const float4*)(Arow + lk + 4));
        w0 = __ldg((const float4*)(Wrow + lk));
        w1 = __ldg((const float4*)(Wrow + lk + 4));
        if (sc) {
            float4 s0 = __ldg((const float4*)(sc + lk));
            float4 s1 = __ldg((const float4*)(sc + lk + 4));
            float4 h0 = __ldg((const float4*)(sh + lk));
            float4 h1 = __ldg((const float4*)(sh + lk + 4));
            a0.x = leaky(a0.x * s0.x + h0.x); a0.y = leaky(a0.y * s0.y + h0.y);
            a0.z = leaky(a0.z * s0.z + h0.z); a0.w = leaky(a0.w * s0.w + h0.w);
            a1.x = leaky(a1.x * s1.x + h1.x); a1.y = leaky(a1.y * s1.y + h1.y);
            a1.z = leaky(a1.z * s1.z + h1.z); a1.w = leaky(a1.w * s1.w + h1.w);
        }
        As[lk + 0][lr] = a0.x; As[lk + 1][lr] = a0.y;
        As[lk + 2][lr] = a0.z; As[lk + 3][lr] = a0.w;
        As[lk + 4][lr] = a1.x; As[lk + 5][lr] = a1.y;
        As[lk + 6][lr] = a1.z; As[lk + 7][lr] = a1.w;
        Bs[lk + 0][ib][txb * 4 + cb] = w0.x; Bs[lk + 1][ib][txb * 4 + cb] = w0.y;
        Bs[lk + 2][ib][txb * 4 + cb] = w0.z; Bs[lk + 3][ib][txb * 4 + cb] = w0.w;
        Bs[lk + 4][ib][txb * 4 + cb] = w1.x; Bs[lk + 5][ib][txb * 4 + cb] = w1.y;
        Bs[lk + 6][ib][txb * 4 + cb] = w1.z; Bs[lk + 7][ib][txb * 4 + cb] = w1.w;
    }
    __syncthreads();

    for (int k0 = 0; k0 < K; k0 += 16) {
        bool more = (k0 + 16) < K;
        if (more) {
            int kn = k0 + 16;
            a0 = __ldg((const float4*)(Arow + kn + lk));
            a1 = __ldg((const float4*)(Arow + kn + lk + 4));
            w0 = __ldg((const float4*)(Wrow + kn + lk));
            w1 = __ldg((const float4*)(Wrow + kn + lk + 4));
            if (sc) {
                float4 s0 = __ldg((const float4*)(sc + kn + lk));
                float4 s1 = __ldg((const float4*)(sc + kn + lk + 4));
                float4 h0 = __ldg((const float4*)(sh + kn + lk));
                float4 h1 = __ldg((const float4*)(sh + kn + lk + 4));
                a0.x = leaky(a0.x * s0.x + h0.x); a0.y = leaky(a0.y * s0.y + h0.y);
                a0.z = leaky(a0.z * s0.z + h0.z); a0.w = leaky(a0.w * s0.w + h0.w);
                a1.x = leaky(a1.x * s1.x + h1.x); a1.y = leaky(a1.y * s1.y + h1.y);
                a1.z = leaky(a1.z * s1.z + h1.z); a1.w = leaky(a1.w * s1.w + h1.w);
            }
        }
#pragma unroll
        for (int kk = 0; kk < 16; kk++) {
            float4 avL = *(const float4*)&As[kk][ty * 8 + 0];
            float4 avH = *(const float4*)&As[kk][ty * 8 + 4];
            float4 b0 = *(const float4*)&Bs[kk][0][tx * 4];
            float4 b1 = *(const float4*)&Bs[kk][1][tx * 4];
            ull ad[8];
            ad[0] = dup2(avL.x); ad[1] = dup2(avL.y);
            ad[2] = dup2(avL.z); ad[3] = dup2(avL.w);
            ad[4] = dup2(avH.x); ad[5] = dup2(avH.y);
            ad[6] = dup2(avH.z); ad[7] = dup2(avH.w);
            ull bp[4];
            bp[0] = pack2(b0.x, b0.y); bp[1] = pack2(b0.z, b0.w);
            bp[2] = pack2(b1.x, b1.y); bp[3] = pack2(b1.z, b1.w);
#pragma unroll
            for (int i = 0; i < 8; i++)
#pragma unroll
                for (int j = 0; j < 4; j++) fma2(acc[i][j], ad[i], bp[j]);
        }
        if (more) {
            __syncthreads();
            As[lk + 0][lr] = a0.x; As[lk + 1][lr] = a0.y;
            As[lk + 2][lr] = a0.z; As[lk + 3][lr] = a0.w;
            As[lk + 4][lr] = a1.x; As[lk + 5][lr] = a1.y;
            As[lk + 6][lr] = a1.z; As[lk + 7][lr] = a1.w;
            Bs[lk + 0][ib][txb * 4 + cb] = w0.x; Bs[lk + 1][ib][txb * 4 + cb] = w0.y;
            Bs[lk + 2][ib][txb * 4 + cb] = w0.z; Bs[lk + 3][ib][txb * 4 + cb] = w0.w;
            Bs[lk + 4][ib][txb * 4 + cb] = w1.x; Bs[lk + 5][ib][txb * 4 + cb] = w1.y;
            Bs[lk + 6][ib][txb * 4 + cb] = w1.z; Bs[lk + 7][ib][txb * 4 + cb] = w1.w;
            __syncthreads();
        }
    }
#pragma unroll
    for (int i = 0; i < 8; i++) {
        int m = bm + ty * 8 + i;
        if (m < M) {
            float2 r0 = up2(acc[i][0]), r1 = up2(acc[i][1]);
            float2 r2 = up2(acc[i][2]), r3 = up2(acc[i][3]);
            float* op = out + (size_t)m * DD + bn + tx * 8;
            *(float4*)(op)     = make_float4(r0.x, r0.y, r1.x, r1.y);
            *(float4*)(op + 4) = make_float4(r2.x, r2.y, r3.x, r3.y);
        }
    }
}

// ---------------- per-edge packed accumulate helper --------------------------
__device__ __forceinline__ void edge_accum(
    ull acc[4], float4 at, ulonglong2 p, ulonglong2 q,
    const ull c0p[4], const ull c1p[4], const ull c2p[4], const ull c3p[4],
    const ull bbp[4])
{
    const ull ABS2 = 0x7fffffff7fffffffull;
    const ull D505 = 0x3f0147ae3f0147aeull;  // dup2(0.505f)
    const ull D495 = 0x3efd70a43efd70a4ull;  // dup2(0.495f)
    ull ax = dup2(at.x), ay = dup2(at.y), az = dup2(at.z), aw = dup2(at.w);
    ull hh[4] = {p.x, p.y, q.x, q.y};
#pragma unroll
    for (int i = 0; i < 4; i++) {
        ull m = add2(hh[i], bbp[i]);
        fma2(m, ax, c0p[i]); fma2(m, ay, c1p[i]);
        fma2(m, az, c2p[i]); fma2(m, aw, c3p[i]);
        ull ab = m & ABS2;
        fma2(acc[i], D505, m);
        fma2(acc[i], D495, ab);
    }
}

// ---------------- CSR gather (permuted edges, packed f32x2, unroll-4) --------
__global__ void gather_kernel(const float* __restrict__ H,
                              const float* __restrict__ C,
                              const float* __restrict__ bc,
                              float* __restrict__ agg,
                              float* __restrict__ bnsum,
                              float* __restrict__ bnsq)
{
    __shared__ float ssum[DD];
    __shared__ float ssq[DD];
    int t = threadIdx.x;
    ssum[t] = 0.f; ssq[t] = 0.f;
    __syncthreads();

    int lane = t & 31;
    int wid = (blockIdx.x * blockDim.x + t) >> 5;
    int nw = (gridDim.x * blockDim.x) >> 5;
    int d0 = lane * 8;

    ull c0p[4], c1p[4], c2p[4], c3p[4], bbp[4];
    {
        ulonglong2 u;
        u = *(const ulonglong2*)(C + 0 * DD + d0);     c0p[0] = u.x; c0p[1] = u.y;
        u = *(const ulonglong2*)(C + 0 * DD + d0 + 4); c0p[2] = u.x; c0p[3] = u.y;
        u = *(const ulonglong2*)(C + 1 * DD + d0);     c1p[0] = u.x; c1p[1] = u.y;
        u = *(const ulonglong2*)(C + 1 * DD + d0 + 4); c1p[2] = u.x; c1p[3] = u.y;
        u = *(const ulonglong2*)(C + 2 * DD + d0);     c2p[0] = u.x; c2p[1] = u.y;
        u = *(const ulonglong2*)(C + 2 * DD + d0 + 4); c2p[2] = u.x; c2p[3] = u.y;
        u = *(const ulonglong2*)(C + 3 * DD + d0);     c3p[0] = u.x; c3p[1] = u.y;
        u = *(const ulonglong2*)(C + 3 * DD + d0 + 4); c3p[2] = u.x; c3p[3] = u.y;
        u = *(const ulonglong2*)(bc + d0);             bbp[0] = u.x; bbp[1] = u.y;
        u = *(const ulonglong2*)(bc + d0 + 4);         bbp[2] = u.x; bbp[3] = u.y;
    }

    float sA[8], qA[8];
#pragma unroll
    for (int i = 0; i < 8; i++) { sA[i] = 0.f; qA[i] = 0.f; }

    for (int n = wid; n < N_NODES; n += nw) {
        int s0 = __ldg(g_start + n);
        int dg = __ldg(g_deg + n);
        ull acc[4] = {0ull, 0ull, 0ull, 0ull};

        int j = 0;
        for (; j + 3 < dg; j += 4) {
            // sequential, L1-hot
            int sa = __ldg(g_srcs + s0 + j);
            int sb = __ldg(g_srcs + s0 + j + 1);
            int sc2 = __ldg(g_srcs + s0 + j + 2);
            int sd = __ldg(g_srcs + s0 + j + 3);
            // random H rows — 8 independent LDG.128 in flight
            const ulonglong2* ha = (const ulonglong2*)(H + (size_t)sa * DD + d0);
            const ulonglong2* hb = (const ulonglong2*)(H + (size_t)sb * DD + d0);
            const ulonglong2* hc = (const ulonglong2*)(H + (size_t)sc2 * DD + d0);
            const ulonglong2* hd = (const ulonglong2*)(H + (size_t)sd * DD + d0);
            ulonglong2 pa = ha[0], qa = ha[1];
            ulonglong2 pb = hb[0], qb = hb[1];
            ulonglong2 pc = hc[0], qc = hc[1];
            ulonglong2 pd = hd[0], qd = hd[1];
            float4 at0 = __ldg((const float4*)g_eas + s0 + j);
            float4 at1 = __ldg((const float4*)g_eas + s0 + j + 1);
            float4 at2 = __ldg((const float4*)g_eas + s0 + j + 2);
            float4 at3 = __ldg((const float4*)g_eas + s0 + j + 3);
            edge_accum(acc, at0, pa, qa, c0p, c1p, c2p, c3p, bbp);
            edge_accum(acc, at1, pb, qb, c0p, c1p, c2p, c3p, bbp);
            edge_accum(acc, at2, pc, qc, c0p, c1p, c2p, c3p, bbp);
            edge_accum(acc, at3, pd, qd, c0p, c1p, c2p, c3p, bbp);
        }
        for (; j < dg; j++) {
            int sa = __ldg(g_srcs + s0 + j);
            float4 at0 = __ldg((const float4*)g_eas + s0 + j);
            const ulonglong2* ha = (const ulonglong2*)(H + (size_t)sa * DD + d0);
            ulonglong2 pa = ha[0], qa = ha[1];
            edge_accum(acc, at0, pa, qa, c0p, c1p, c2p, c3p, bbp);
        }

        ulonglong2* op = (ulonglong2*)(agg + (size_t)n * DD + d0);
        op[0] = make_ulonglong2(acc[0], acc[1]);
        op[1] = make_ulonglong2(acc[2], acc[3]);

#pragma unroll
        for (int i = 0; i < 4; i++) {
            float2 f = up2(acc[i]);
            sA[2 * i]     += f.x;  qA[2 * i]     += f.x * f.x;
            sA[2 * i + 1] += f.y;  qA[2 * i + 1] += f.y * f.y;
        }
    }
#pragma unroll
    for (int i = 0; i < 8; i++) {
        atomicAdd(&ssum[d0 + i], sA[i]);
        atomicAdd(&ssq[d0 + i], qA[i]);
    }
    __syncthreads();
    atomicAdd(&bnsum[t], ssum[t]);
    atomicAdd(&bnsq[t], ssq[t]);
}

// ---------------- BN scale/shift from stats ----------------------------------
__global__ void bnsc_kernel(const float* __restrict__ w, const float* __restrict__ b,
                            const float* __restrict__ bnsum, const float* __restrict__ bnsq)
{
    int c = threadIdx.x;
    const float invN = 1.f / (float)N_NODES;
    float m = bnsum[c] * invN;
    float var = bnsq[c] * invN - m * m;
    float s = w[c] * rsqrtf(var + EPS);
    g_sc[c] = s;
    g_sh[c] = b[c] - m * s;
}

// ---------------- BN2 apply + leaky (in place) + gate + segment max ----------
__global__ void bn_apply_gate(float* __restrict__ X,
                              const float* __restrict__ gw,
                              const float* __restrict__ gb,
                              const int* __restrict__ batch)
{
    int wid = (blockIdx.x * blockDim.x + threadIdx.x) >> 5;
    int lane = threadIdx.x & 31;
    if (wid >= N_NODES) return;
    int d0 = lane * 8;
    float4* xp = (float4*)(X + (size_t)wid * DD + d0);
    float4 h0 = xp[0], h1 = xp[1];
    float v[8] = {h0.x, h0.y, h0.z, h0.w, h1.x, h1.y, h1.z, h1.w};
    float gsum = 0.f;
#pragma unroll
    for (int i = 0; i < 8; i++) {
        int ch = d0 + i;
        float x = leaky(v[i] * g_sc[ch] + g_sh[ch]);
        v[i] = x;
        gsum += x * __ldg(gw + ch);
    }
    xp[0] = make_float4(v[0], v[1], v[2], v[3]);
    xp[1] = make_float4(v[4], v[5], v[6], v[7]);
#pragma unroll
    for (int off = 16; off; off >>= 1) gsum += __shfl_xor_sync(0xffffffffu, gsum, off);
    if (lane == 0) {
        gsum += __ldg(gb);
        g_gate[wid] = gsum;
        atomicMax(&g_gmax[__ldg(batch + wid)], enc_f(gsum));
    }
}

// ---------------- exp + segment sum ------------------------------------------
__global__ void expsum_kernel(const int* __restrict__ batch)
{
    int n = blockIdx.x * blockDim.x + threadIdx.x;
    if (n >= N_NODES) return;
    int b = __ldg(batch + n);
    float gm = dec_f(g_gmax[b]);
    float e = __expf(g_gate[n] - gm);
    g_e[n] = e;
    atomicAdd(&g_denom[b], e);
}

// ---------------- final weighted aggregation ---------------------------------
__global__ void final_kernel(const float* __restrict__ x2,
                             const int* __restrict__ batch,
                             float* __restrict__ out)
{
    int wid = (blockIdx.x * blockDim.x + threadIdx.x) >> 5;
    int lane = threadIdx.x & 31;
    if (wid >= N_NODES) return;
    int b = __ldg(batch + wid);
    float w = g_e[wid] / g_denom[b];
    int d0 = lane * 8;
    const float4* xp = (const float4*)(x2 + (size_t)wid * DD + d0);
    float4 a0 = __ldg(xp), a1 = __ldg(xp + 1);
    float* op = out + (size_t)b * DD + d0;
    red_add_v4(op,     w * a0.x, w * a0.y, w * a0.z, w * a0.w);
    red_add_v4(op + 4, w * a1.x, w * a1.y, w * a1.z, w * a1.w);
}

// ---------------- launch -----------------------------------------------------
extern "C" void kernel_launch(void* const* d_in, const int* in_sizes, int n_in,
                              void* d_out, int out_size)
{
    const int*   node_ids  = (const int*)d_in[0];
    const int*   edge_index= (const int*)d_in[1];
    const float* edge_attr = (const float*)d_in[2];
    const int*   batch     = (const int*)d_in[3];
    const float* emb       = (const float*)d_in[4];
    const float* c1_lin2_w = (const float*)d_in[5];
    const float* c1_lin2_b = (const float*)d_in[6];
    const float* c1_lin_w  = (const float*)d_in[7];
    const float* c1_lin_b  = (const float*)d_in[8];
    const float* bn1_w     = (const float*)d_in[9];
    const float* bn1_b     = (const float*)d_in[10];
    const float* c2_lin2_w = (const float*)d_in[11];
    const float* c2_lin2_b = (const float*)d_in[12];
    const float* c2_lin_w  = (const float*)d_in[13];
    const float* c2_lin_b  = (const float*)d_in[14];
    const float* bn2_w     = (const float*)d_in[15];
    const float* bn2_b     = (const float*)d_in[16];
    const float* gate_w    = (const float*)d_in[17];
    const float* gate_b    = (const float*)d_in[18];
    float* out = (float*)d_out;

    const int* src = edge_index;
    const int* dst = edge_index + N_EDGES;

    float *pA, *pB, *pC1, *pbc1, *pC2, *pbc2, *psc, *psh;
    float *pbs1, *pbq1, *pbs2, *pbq2;
    cudaGetSymbolAddress((void**)&pA,   g_bufA);
    cudaGetSymbolAddress((void**)&pB,   g_bufB);
    cudaGetSymbolAddress((void**)&pC1,  g_C1);
    cudaGetSymbolAddress((void**)&pbc1, g_bc1);
    cudaGetSymbolAddress((void**)&pC2,  g_C2);
    cudaGetSymbolAddress((void**)&pbc2, g_bc2);
    cudaGetSymbolAddress((void**)&psc,  g_sc);
    cudaGetSymbolAddress((void**)&psh,  g_sh);
    cudaGetSymbolAddress((void**)&pbs1, g_bnsum1);
    cudaGetSymbolAddress((void**)&pbq1, g_bnsq1);
    cudaGetSymbolAddress((void**)&pbs2, g_bnsum2);
    cudaGetSymbolAddress((void**)&pbq2, g_bnsq2);

    // ---- init ----
    zero_init<<<NSB, 256>>>();
    zero_f<<<(out_size + 255) / 256, 256>>>(out, out_size);

    // ---- CSR build (dst-sorted, permuted src + edge_attr) ----
    hist_kernel<<<(N_EDGES + 255) / 256, 256>>>(dst);
    scan1_kernel<<<NSB, 256>>>();
    scan2_kernel<<<1, 256>>>();
    scan3_kernel<<<NSB, 256>>>();
    fill_kernel<<<(N_EDGES + 255) / 256, 256>>>(src, dst, edge_attr);

    // ---- combined edge matrices ----
    combine_kernel<<<1, 256>>>(c1_lin2_w, c1_lin2_b, c1_lin_w, c1_lin_b,
                               c2_lin2_w, c2_lin2_b, c2_lin_w, c2_lin_b);

    dim3 gg((N_NODES + 127) / 128, DD / 128);

    // ---- layer 1: H1 = emb[node_ids] @ W1^T ----
    gemm_v3<<<gg, 256>>>(emb, node_ids, nullptr, nullptr, c1_lin_w, pA, N_NODES, F_IN);

    // ---- conv1 gather -> agg1 (bufB) + bn1 stats ----
    gather_kernel<<<2048, 256>>>(pA, pC1, pbc1, pB, pbs1, pbq1);
    bnsc_kernel<<<1, 256>>>(bn1_w, bn1_b, pbs1, pbq1);

    // ---- layer 2: H2 = leaky(bn1(agg1)) @ W2^T  (BN fused into A-load) ----
    gemm_v3<<<gg, 256>>>(pB, nullptr, psc, psh, c2_lin_w, pA, N_NODES, DD);

    // ---- conv2 gather -> agg2 (bufB) + bn2 stats ----
    gather_kernel<<<2048, 256>>>(pA, pC2, pbc2, pB, pbs2, pbq2);
    bnsc_kernel<<<1, 256>>>(bn2_w, bn2_b, pbs2, pbq2);

    // ---- bn2 apply (in place) + gate + segment max ----
    int nb = (N_NODES * 32 + 255) / 256;
    bn_apply_gate<<<nb, 256>>>(pB, gate_w, gate_b, batch);

    // ---- softmax + weighted aggregation ----
    expsum_kernel<<<(N_NODES + 255) / 256, 256>>>(batch);
    final_kernel<<<nb, 256>>>(pB, batch, out);
}

// round 6
// speedup vs baseline: 2.3578x; 1.1249x over previous
#include <cuda_runtime.h>
#include <cstdint>

#define N_NODES  50000
#define N_EDGES  800000
#define N_GRAPHS 512
#define F_IN     128
#define DD       256
#define EPS      1e-5f
#define NEG_SLOPE 0.01f
#define NSB      196          // ceil(N_NODES/256) scan blocks

typedef unsigned long long ull;

// ---------------- scratch (device globals; no allocation allowed) ----------
__device__ float g_bufA[N_NODES * DD];   // H1 -> H2
__device__ float g_bufB[N_NODES * DD];   // agg1 -> agg2 -> x2 (in place)
__device__ float g_C1[4 * DD];
__device__ float g_bc1[DD];
__device__ float g_C2[4 * DD];
__device__ float g_bc2[DD];
__device__ float g_bnsum1[DD];
__device__ float g_bnsq1[DD];
__device__ float g_bnsum2[DD];
__device__ float g_bnsq2[DD];
__device__ float g_sc[DD];
__device__ float g_sh[DD];
__device__ unsigned g_gmax[N_GRAPHS];
__device__ float g_denom[N_GRAPHS];
__device__ float g_gate[N_NODES];
__device__ float g_e[N_NODES];
// CSR (dst-sorted, with permuted src and edge_attr)
__device__ int    g_deg[N_NODES];
__device__ int    g_start[N_NODES];
__device__ int    g_cursor[N_NODES];
__device__ int    g_srcs[N_EDGES];
__device__ float4 g_eas[N_EDGES];
__device__ int    g_part[NSB];
__device__ int    g_part2[NSB];

// ---------------- helpers ---------------------------------------------------
__device__ __forceinline__ float leaky(float v) {
    return v >= 0.f ? v : NEG_SLOPE * v;
}
__device__ __forceinline__ unsigned enc_f(float x) {
    unsigned u = __float_as_uint(x);
    return (u & 0x80000000u) ? ~u : (u | 0x80000000u);
}
__device__ __forceinline__ float dec_f(unsigned u) {
    return (u & 0x80000000u) ? __uint_as_float(u ^ 0x80000000u) : __uint_as_float(~u);
}
__device__ __forceinline__ void red_add_v4(float* p, float a, float b, float c, float d) {
    asm volatile("red.global.add.v4.f32 [%0], {%1, %2, %3, %4};"
                 :: "l"(p), "f"(a), "f"(b), "f"(c), "f"(d) : "memory");
}
__device__ __forceinline__ ull dup2(float x) {
    ull r; unsigned u = __float_as_uint(x);
    asm("mov.b64 %0, {%1, %1};" : "=l"(r) : "r"(u));
    return r;
}
__device__ __forceinline__ void fma2(ull& d, ull a, ull b) {
    asm("fma.rn.f32x2 %0, %1, %2, %0;" : "+l"(d) : "l"(a), "l"(b));
}
__device__ __forceinline__ ull add2(ull a, ull b) {
    ull r;
    asm("add.rn.f32x2 %0, %1, %2;" : "=l"(r) : "l"(a), "l"(b));
    return r;
}
__device__ __forceinline__ float2 up2(ull v) {
    float2 f; asm("mov.b64 {%0, %1}, %2;" : "=f"(f.x), "=f"(f.y) : "l"(v));
    return f;
}
__device__ __forceinline__ unsigned tf32c(float x) {
    unsigned r;
    asm("cvt.rna.tf32.f32 %0, %1;" : "=r"(r) : "f"(x));
    return r;
}
__device__ __forceinline__ void mma_tf32(float d[4], const unsigned a[4],
                                         unsigned b0, unsigned b1) {
    asm volatile(
        "mma.sync.aligned.m16n8k8.row.col.f32.tf32.tf32.f32 "
        "{%0,%1,%2,%3}, {%4,%5,%6,%7}, {%8,%9}, {%0,%1,%2,%3};"
        : "+f"(d[0]), "+f"(d[1]), "+f"(d[2]), "+f"(d[3])
        : "r"(a[0]), "r"(a[1]), "r"(a[2]), "r"(a[3]), "r"(b0), "r"(b1));
}

// ---------------- zero / init kernels ---------------------------------------
__global__ void zero_f(float* p, int n) {
    int i = blockIdx.x * blockDim.x + threadIdx.x;
    int stride = gridDim.x * blockDim.x;
    for (; i < n; i += stride) p[i] = 0.f;
}
__global__ void zero_init() {
    int i = blockIdx.x * blockDim.x + threadIdx.x;
    if (i < N_NODES) g_deg[i] = 0;
    if (i < DD) {
        g_bnsum1[i] = 0.f; g_bnsq1[i] = 0.f;
        g_bnsum2[i] = 0.f; g_bnsq2[i] = 0.f;
    }
    if (i < N_GRAPHS) { g_gmax[i] = 0u; g_denom[i] = 0.f; }
}

// ---------------- CSR build --------------------------------------------------
__global__ void hist_kernel(const int* __restrict__ dst) {
    int e = blockIdx.x * blockDim.x + threadIdx.x;
    if (e < N_EDGES) atomicAdd(&g_deg[__ldg(dst + e)], 1);
}
__global__ void scan1_kernel() {
    __shared__ int sh[256];
    int i = blockIdx.x * 256 + threadIdx.x;
    int v = (i < N_NODES) ? g_deg[i] : 0;
    sh[threadIdx.x] = v; __syncthreads();
#pragma unroll
    for (int off = 1; off < 256; off <<= 1) {
        int tv = (threadIdx.x >= off) ? sh[threadIdx.x - off] : 0;
        __syncthreads();
        sh[threadIdx.x] += tv;
        __syncthreads();
    }
    if (i < N_NODES) g_start[i] = sh[threadIdx.x] - v;
    if (threadIdx.x == 255) g_part[blockIdx.x] = sh[255];
}
__global__ void scan2_kernel() {
    __shared__ int sh[256];
    int t = threadIdx.x;
    int v = (t < NSB) ? g_part[t] : 0;
    sh[t] = v; __syncthreads();
#pragma unroll
    for (int off = 1; off < 256; off <<= 1) {
        int tv = (t >= off) ? sh[t - off] : 0;
        __syncthreads();
        sh[t] += tv;
        __syncthreads();
    }
    if (t < NSB) g_part2[t] = sh[t] - v;
}
__global__ void scan3_kernel() {
    int i = blockIdx.x * 256 + threadIdx.x;
    if (i < N_NODES) {
        int s = g_start[i] + g_part2[blockIdx.x];
        g_start[i] = s;
        g_cursor[i] = s;
    }
}
__global__ void fill_kernel(const int* __restrict__ src,
                            const int* __restrict__ dst,
                            const float* __restrict__ ea) {
    int e = blockIdx.x * blockDim.x + threadIdx.x;
    if (e < N_EDGES) {
        int d = __ldg(dst + e);
        int p = atomicAdd(&g_cursor[d], 1);
        g_srcs[p] = __ldg(src + e);
        g_eas[p] = __ldg((const float4*)ea + e);
    }
}

// ---------------- combined edge matrices ------------------------------------
__global__ void combine_kernel(
    const float* __restrict__ l2w1, const float* __restrict__ l2b1,
    const float* __restrict__ lw1,  const float* __restrict__ lb1,
    const float* __restrict__ l2w2, const float* __restrict__ l2b2,
    const float* __restrict__ lw2,  const float* __restrict__ lb2)
{
    int d = threadIdx.x;   // 256 threads
    {
        float a0 = 0.f, a1 = 0.f, a2 = 0.f, a3 = 0.f, bb = 0.f;
        for (int f = 0; f < F_IN; f++) {
            float w = lw1[d * F_IN + f];
            float4 l2 = *(const float4*)(l2w1 + f * 4);
            a0 += l2.x * w; a1 += l2.y * w; a2 += l2.z * w; a3 += l2.w * w;
            bb += l2b1[f] * w;
        }
        g_C1[0 * DD + d] = a0; g_C1[1 * DD + d] = a1;
        g_C1[2 * DD + d] = a2; g_C1[3 * DD + d] = a3;
        g_bc1[d] = bb + lb1[d];
    }
    {
        float a0 = 0.f, a1 = 0.f, a2 = 0.f, a3 = 0.f, bb = 0.f;
        for (int f = 0; f < DD; f++) {
            float w = lw2[d * DD + f];
            float4 l2 = *(const float4*)(l2w2 + f * 4);
            a0 += l2.x * w; a1 += l2.y * w; a2 += l2.z * w; a3 += l2.w * w;
            bb += l2b2[f] * w;
        }
        g_C2[0 * DD + d] = a0; g_C2[1 * DD + d] = a1;
        g_C2[2 * DD + d] = a2; g_C2[3 * DD + d] = a3;
        g_bc2[d] = bb + lb2[d];
    }
}

// ---------------- GEMM (tf32 tensor cores) -----------------------------------
// out[m][n] = sum_k A'[m][k] * W[n][k];  A' = leaky(A*sc + sh) if sc != null.
// Block tile 128x128 (grid.y = 2 for N=256), 8 warps, warp tile 32x64,
// m16n8k8 tf32 atoms. Smem [row][36] padded layout -> conflict-free frag loads.
__global__ void __launch_bounds__(256)
gemm_tf32(const float* __restrict__ A, const int* __restrict__ idx,
          const float* __restrict__ sc, const float* __restrict__ sh,
          const float* __restrict__ W, float* __restrict__ out,
          int M, int K)
{
    __shared__ unsigned As[128 * 36];
    __shared__ unsigned Bs[128 * 36];
    int t = threadIdx.x;
    int lane = t & 31;
    int wid = t >> 5;
    int wm = wid & 3, wn = wid >> 2;       // warp tile: rows wm*32, cols wn*64
    int bm = blockIdx.x * 128;
    int bn = blockIdx.y * 128;

    int lrow = t >> 1;                     // 0..127 (both A-row and B-row)
    int lkh = (t & 1) * 16;                // k-half: 0 or 16

    int m0 = bm + lrow;
    int mc = m0 < M ? m0 : (M - 1);
    int arow = idx ? __ldg(idx + mc) : mc;
    const float* Arow = A + (size_t)arow * K;
    const float* Wrow = W + (size_t)(bn + lrow) * K;

    float d[2][8][4];
#pragma unroll
    for (int i = 0; i < 2; i++)
#pragma unroll
        for (int j = 0; j < 8; j++)
#pragma unroll
            for (int c = 0; c < 4; c++) d[i][j][c] = 0.f;

    float4 va[4], vb[4];

    // stage loaders (register double-buffer)
    auto load_stage = [&](int kc) {
#pragma unroll
        for (int q = 0; q < 4; q++) {
            va[q] = __ldg((const float4*)(Arow + kc + lkh + q * 4));
            vb[q] = __ldg((const float4*)(Wrow + kc + lkh + q * 4));
        }
        if (sc) {
#pragma unroll
            for (int q = 0; q < 4; q++) {
                int ch = kc + lkh + q * 4;
                float4 s = __ldg((const float4*)(sc + ch));
                float4 h = __ldg((const float4*)(sh + ch));
                va[q].x = leaky(va[q].x * s.x + h.x);
                va[q].y = leaky(va[q].y * s.y + h.y);
                va[q].z = leaky(va[q].z * s.z + h.z);
                va[q].w = leaky(va[q].w * s.w + h.w);
            }
        }
    };
    auto store_stage = [&]() {
        unsigned* ap = As + lrow * 36 + lkh;
        unsigned* bp = Bs + lrow * 36 + lkh;
#pragma unroll
        for (int q = 0; q < 4; q++) {
            *(uint4*)(ap + q * 4) = make_uint4(tf32c(va[q].x), tf32c(va[q].y),
                                               tf32c(va[q].z), tf32c(va[q].w));
            *(uint4*)(bp + q * 4) = make_uint4(tf32c(vb[q].x), tf32c(vb[q].y),
                                               tf32c(vb[q].z), tf32c(vb[q].w));
        }
    };

    load_stage(0);
    store_stage();
    __syncthreads();

    for (int kc = 0; kc < K; kc += 32) {
        bool more = (kc + 32) < K;
        if (more) load_stage(kc + 32);
#pragma unroll
        for (int ks = 0; ks < 4; ks++) {
            int k0 = ks * 8;
            unsigned a[2][4];
            int ra = (wm * 32 + (lane >> 2)) * 36 + k0 + (lane & 3);
#pragma unroll
            for (int i = 0; i < 2; i++) {
                int base = ra + i * 16 * 36;
                a[i][0] = As[base];
                a[i][1] = As[base + 8 * 36];
                a[i][2] = As[base + 4];
                a[i][3] = As[base + 8 * 36 + 4];
            }
            int rb = (wn * 64 + (lane >> 2)) * 36 + k0 + (lane & 3);
#pragma unroll
            for (int j = 0; j < 8; j++) {
                unsigned b0 = Bs[rb + j * 8 * 36];
                unsigned b1 = Bs[rb + j * 8 * 36 + 4];
                mma_tf32(d[0][j], a[0], b0, b1);
                mma_tf32(d[1][j], a[1], b0, b1);
            }
        }
        if (more) {
            __syncthreads();
            store_stage();
            __syncthreads();
        }
    }

    // epilogue
#pragma unroll
    for (int i = 0; i < 2; i++) {
        int rg0 = bm + wm * 32 + i * 16 + (lane >> 2);
        int rg1 = rg0 + 8;
#pragma unroll
        for (int j = 0; j < 8; j++) {
            int col = bn + wn * 64 + j * 8 + (lane & 3) * 2;
            if (rg0 < M)
                *(float2*)(out + (size_t)rg0 * DD + col) = make_float2(d[i][j][0], d[i][j][1]);
            if (rg1 < M)
                *(float2*)(out + (size_t)rg1 * DD + col) = make_float2(d[i][j][2], d[i][j][3]);
        }
    }
}

// ---------------- per-edge packed accumulate helper --------------------------
__device__ __forceinline__ void edge_accum(
    ull acc[4], float4 at, ulonglong2 p, ulonglong2 q,
    const ull c0p[4], const ull c1p[4], const ull c2p[4], const ull c3p[4],
    const ull bbp[4])
{
    const ull ABS2 = 0x7fffffff7fffffffull;
    const ull D505 = 0x3f0147ae3f0147aeull;  // dup2(0.505f)
    const ull D495 = 0x3efd70a43efd70a4ull;  // dup2(0.495f)
    ull ax = dup2(at.x), ay = dup2(at.y), az = dup2(at.z), aw = dup2(at.w);
    ull hh[4] = {p.x, p.y, q.x, q.y};
#pragma unroll
    for (int i = 0; i < 4; i++) {
        ull m = add2(hh[i], bbp[i]);
        fma2(m, ax, c0p[i]); fma2(m, ay, c1p[i]);
        fma2(m, az, c2p[i]); fma2(m, aw, c3p[i]);
        ull ab = m & ABS2;
        fma2(acc[i], D505, m);
        fma2(acc[i], D495, ab);
    }
}

// ---------------- CSR gather (permuted edges, packed f32x2, unroll-4) --------
__global__ void gather_kernel(const float* __restrict__ H,
                              const float* __restrict__ C,
                              const float* __restrict__ bc,
                              float* __restrict__ agg,
                              float* __restrict__ bnsum,
                              float* __restrict__ bnsq)
{
    __shared__ float ssum[DD];
    __shared__ float ssq[DD];
    int t = threadIdx.x;
    ssum[t] = 0.f; ssq[t] = 0.f;
    __syncthreads();

    int lane = t & 31;
    int wid = (blockIdx.x * blockDim.x + t) >> 5;
    int nw = (gridDim.x * blockDim.x) >> 5;
    int d0 = lane * 8;

    ull c0p[4], c1p[4], c2p[4], c3p[4], bbp[4];
    {
        ulonglong2 u;
        u = *(const ulonglong2*)(C + 0 * DD + d0);     c0p[0] = u.x; c0p[1] = u.y;
        u = *(const ulonglong2*)(C + 0 * DD + d0 + 4); c0p[2] = u.x; c0p[3] = u.y;
        u = *(const ulonglong2*)(C + 1 * DD + d0);     c1p[0] = u.x; c1p[1] = u.y;
        u = *(const ulonglong2*)(C + 1 * DD + d0 + 4); c1p[2] = u.x; c1p[3] = u.y;
        u = *(const ulonglong2*)(C + 2 * DD + d0);     c2p[0] = u.x; c2p[1] = u.y;
        u = *(const ulonglong2*)(C + 2 * DD + d0 + 4); c2p[2] = u.x; c2p[3] = u.y;
        u = *(const ulonglong2*)(C + 3 * DD + d0);     c3p[0] = u.x; c3p[1] = u.y;
        u = *(const ulonglong2*)(C + 3 * DD + d0 + 4); c3p[2] = u.x; c3p[3] = u.y;
        u = *(const ulonglong2*)(bc + d0);             bbp[0] = u.x; bbp[1] = u.y;
        u = *(const ulonglong2*)(bc + d0 + 4);         bbp[2] = u.x; bbp[3] = u.y;
    }

    float sA[8], qA[8];
#pragma unroll
    for (int i = 0; i < 8; i++) { sA[i] = 0.f; qA[i] = 0.f; }

    for (int n = wid; n < N_NODES; n += nw) {
        int s0 = __ldg(g_start + n);
        int dg = __ldg(g_deg + n);
        ull acc[4] = {0ull, 0ull, 0ull, 0ull};

        int j = 0;
        for (; j + 3 < dg; j += 4) {
            int sa = __ldg(g_srcs + s0 + j);
            int sb = __ldg(g_srcs + s0 + j + 1);
            int sc2 = __ldg(g_srcs + s0 + j + 2);
            int sd = __ldg(g_srcs + s0 + j + 3);
            const ulonglong2* ha = (const ulonglong2*)(H + (size_t)sa * DD + d0);
            const ulonglong2* hb = (const ulonglong2*)(H + (size_t)sb * DD + d0);
            const ulonglong2* hc = (const ulonglong2*)(H + (size_t)sc2 * DD + d0);
            const ulonglong2* hd = (const ulonglong2*)(H + (size_t)sd * DD + d0);
            ulonglong2 pa = ha[0], qa = ha[1];
            ulonglong2 pb = hb[0], qb = hb[1];
            ulonglong2 pc = hc[0], qc = hc[1];
            ulonglong2 pd = hd[0], qd = hd[1];
            float4 at0 = __ldg((const float4*)g_eas + s0 + j);
            float4 at1 = __ldg((const float4*)g_eas + s0 + j + 1);
            float4 at2 = __ldg((const float4*)g_eas + s0 + j + 2);
            float4 at3 = __ldg((const float4*)g_eas + s0 + j + 3);
            edge_accum(acc, at0, pa, qa, c0p, c1p, c2p, c3p, bbp);
            edge_accum(acc, at1, pb, qb, c0p, c1p, c2p, c3p, bbp);
            edge_accum(acc, at2, pc, qc, c0p, c1p, c2p, c3p, bbp);
            edge_accum(acc, at3, pd, qd, c0p, c1p, c2p, c3p, bbp);
        }
        for (; j < dg; j++) {
            int sa = __ldg(g_srcs + s0 + j);
            float4 at0 = __ldg((const float4*)g_eas + s0 + j);
            const ulonglong2* ha = (const ulonglong2*)(H + (size_t)sa * DD + d0);
            ulonglong2 pa = ha[0], qa = ha[1];
            edge_accum(acc, at0, pa, qa, c0p, c1p, c2p, c3p, bbp);
        }

        ulonglong2* op = (ulonglong2*)(agg + (size_t)n * DD + d0);
        op[0] = make_ulonglong2(acc[0], acc[1]);
        op[1] = make_ulonglong2(acc[2], acc[3]);

#pragma unroll
        for (int i = 0; i < 4; i++) {
            float2 f = up2(acc[i]);
            sA[2 * i]     += f.x;  qA[2 * i]     += f.x * f.x;
            sA[2 * i + 1] += f.y;  qA[2 * i + 1] += f.y * f.y;
        }
    }
#pragma unroll
    for (int i = 0; i < 8; i++) {
        atomicAdd(&ssum[d0 + i], sA[i]);
        atomicAdd(&ssq[d0 + i], qA[i]);
    }
    __syncthreads();
    atomicAdd(&bnsum[t], ssum[t]);
    atomicAdd(&bnsq[t], ssq[t]);
}

// ---------------- BN scale/shift from stats ----------------------------------
__global__ void bnsc_kernel(const float* __restrict__ w, const float* __restrict__ b,
                            const float* __restrict__ bnsum, const float* __restrict__ bnsq)
{
    int c = threadIdx.x;
    const float invN = 1.f / (float)N_NODES;
    float m = bnsum[c] * invN;
    float var = bnsq[c] * invN - m * m;
    float s = w[c] * rsqrtf(var + EPS);
    g_sc[c] = s;
    g_sh[c] = b[c] - m * s;
}

// ---------------- BN2 apply + leaky (in place) + gate + segment max ----------
__global__ void bn_apply_gate(float* __restrict__ X,
                              const float* __restrict__ gw,
                              const float* __restrict__ gb,
                              const int* __restrict__ batch)
{
    int wid = (blockIdx.x * blockDim.x + threadIdx.x) >> 5;
    int lane = threadIdx.x & 31;
    if (wid >= N_NODES) return;
    int d0 = lane * 8;
    float4* xp = (float4*)(X + (size_t)wid * DD + d0);
    float4 h0 = xp[0], h1 = xp[1];
    float v[8] = {h0.x, h0.y, h0.z, h0.w, h1.x, h1.y, h1.z, h1.w};
    float gsum = 0.f;
#pragma unroll
    for (int i = 0; i < 8; i++) {
        int ch = d0 + i;
        float x = leaky(v[i] * g_sc[ch] + g_sh[ch]);
        v[i] = x;
        gsum += x * __ldg(gw + ch);
    }
    xp[0] = make_float4(v[0], v[1], v[2], v[3]);
    xp[1] = make_float4(v[4], v[5], v[6], v[7]);
#pragma unroll
    for (int off = 16; off; off >>= 1) gsum += __shfl_xor_sync(0xffffffffu, gsum, off);
    if (lane == 0) {
        gsum += __ldg(gb);
        g_gate[wid] = gsum;
        atomicMax(&g_gmax[__ldg(batch + wid)], enc_f(gsum));
    }
}

// ---------------- exp + segment sum ------------------------------------------
__global__ void expsum_kernel(const int* __restrict__ batch)
{
    int n = blockIdx.x * blockDim.x + threadIdx.x;
    if (n >= N_NODES) return;
    int b = __ldg(batch + n);
    float gm = dec_f(g_gmax[b]);
    float e = __expf(g_gate[n] - gm);
    g_e[n] = e;
    atomicAdd(&g_denom[b], e);
}

// ---------------- final weighted aggregation ---------------------------------
__global__ void final_kernel(const float* __restrict__ x2,
                             const int* __restrict__ batch,
                             float* __restrict__ out)
{
    int wid = (blockIdx.x * blockDim.x + threadIdx.x) >> 5;
    int lane = threadIdx.x & 31;
    if (wid >= N_NODES) return;
    int b = __ldg(batch + wid);
    float w = g_e[wid] / g_denom[b];
    int d0 = lane * 8;
    const float4* xp = (const float4*)(x2 + (size_t)wid * DD + d0);
    float4 a0 = __ldg(xp), a1 = __ldg(xp + 1);
    float* op = out + (size_t)b * DD + d0;
    red_add_v4(op,     w * a0.x, w * a0.y, w * a0.z, w * a0.w);
    red_add_v4(op + 4, w * a1.x, w * a1.y, w * a1.z, w * a1.w);
}

// ---------------- launch -----------------------------------------------------
extern "C" void kernel_launch(void* const* d_in, const int* in_sizes, int n_in,
                              void* d_out, int out_size)
{
    const int*   node_ids  = (const int*)d_in[0];
    const int*   edge_index= (const int*)d_in[1];
    const float* edge_attr = (const float*)d_in[2];
    const int*   batch     = (const int*)d_in[3];
    const float* emb       = (const float*)d_in[4];
    const float* c1_lin2_w = (const float*)d_in[5];
    const float* c1_lin2_b = (const float*)d_in[6];
    const float* c1_lin_w  = (const float*)d_in[7];
    const float* c1_lin_b  = (const float*)d_in[8];
    const float* bn1_w     = (const float*)d_in[9];
    const float* bn1_b     = (const float*)d_in[10];
    const float* c2_lin2_w = (const float*)d_in[11];
    const float* c2_lin2_b = (const float*)d_in[12];
    const float* c2_lin_w  = (const float*)d_in[13];
    const float* c2_lin_b  = (const float*)d_in[14];
    const float* bn2_w     = (const float*)d_in[15];
    const float* bn2_b     = (const float*)d_in[16];
    const float* gate_w    = (const float*)d_in[17];
    const float* gate_b    = (const float*)d_in[18];
    float* out = (float*)d_out;

    const int* src = edge_index;
    const int* dst = edge_index + N_EDGES;

    float *pA, *pB, *pC1, *pbc1, *pC2, *pbc2, *psc, *psh;
    float *pbs1, *pbq1, *pbs2, *pbq2;
    cudaGetSymbolAddress((void**)&pA,   g_bufA);
    cudaGetSymbolAddress((void**)&pB,   g_bufB);
    cudaGetSymbolAddress((void**)&pC1,  g_C1);
    cudaGetSymbolAddress((void**)&pbc1, g_bc1);
    cudaGetSymbolAddress((void**)&pC2,  g_C2);
    cudaGetSymbolAddress((void**)&pbc2, g_bc2);
    cudaGetSymbolAddress((void**)&psc,  g_sc);
    cudaGetSymbolAddress((void**)&psh,  g_sh);
    cudaGetSymbolAddress((void**)&pbs1, g_bnsum1);
    cudaGetSymbolAddress((void**)&pbq1, g_bnsq1);
    cudaGetSymbolAddress((void**)&pbs2, g_bnsum2);
    cudaGetSymbolAddress((void**)&pbq2, g_bnsq2);

    // ---- init ----
    zero_init<<<NSB, 256>>>();
    zero_f<<<(out_size + 255) / 256, 256>>>(out, out_size);

    // ---- CSR build (dst-sorted, permuted src + edge_attr) ----
    hist_kernel<<<(N_EDGES + 255) / 256, 256>>>(dst);
    scan1_kernel<<<NSB, 256>>>();
    scan2_kernel<<<1, 256>>>();
    scan3_kernel<<<NSB, 256>>>();
    fill_kernel<<<(N_EDGES + 255) / 256, 256>>>(src, dst, edge_attr);

    // ---- combined edge matrices ----
    combine_kernel<<<1, 256>>>(c1_lin2_w, c1_lin2_b, c1_lin_w, c1_lin_b,
                               c2_lin2_w, c2_lin2_b, c2_lin_w, c2_lin_b);

    dim3 gg((N_NODES + 127) / 128, DD / 128);

    // ---- layer 1: H1 = emb[node_ids] @ W1^T (tf32 tensor cores) ----
    gemm_tf32<<<gg, 256>>>(emb, node_ids, nullptr, nullptr, c1_lin_w, pA, N_NODES, F_IN);

    // ---- conv1 gather -> agg1 (bufB) + bn1 stats ----
    gather_kernel<<<2048, 256>>>(pA, pC1, pbc1, pB, pbs1, pbq1);
    bnsc_kernel<<<1, 256>>>(bn1_w, bn1_b, pbs1, pbq1);

    // ---- layer 2: H2 = leaky(bn1(agg1)) @ W2^T  (BN fused into A-load) ----
    gemm_tf32<<<gg, 256>>>(pB, nullptr, psc, psh, c2_lin_w, pA, N_NODES, DD);

    // ---- conv2 gather -> agg2 (bufB) + bn2 stats ----
    gather_kernel<<<2048, 256>>>(pA, pC2, pbc2, pB, pbs2, pbq2);
    bnsc_kernel<<<1, 256>>>(bn2_w, bn2_b, pbs2, pbq2);

    // ---- bn2 apply (in place) + gate + segment max ----
    int nb = (N_NODES * 32 + 255) / 256;
    bn_apply_gate<<<nb, 256>>>(pB, gate_w, gate_b, batch);

    // ---- softmax + weighted aggregation ----
    expsum_kernel<<<(N_NODES + 255) / 256, 256>>>(batch);
    final_kernel<<<nb, 256>>>(pB, batch, out);
}

// round 7
// speedup vs baseline: 3.0455x; 1.2917x over previous
#include <cuda_runtime.h>
#include <cstdint>

#define N_NODES  50000
#define N_EDGES  800000
#define N_GRAPHS 512
#define F_IN     128
#define DD       256
#define EPS      1e-5f
#define NEG_SLOPE 0.01f
#define NSB      196          // ceil(N_NODES/256) scan blocks

typedef unsigned long long ull;

// ---------------- scratch (device globals; no allocation allowed) ----------
__device__ float g_bufA[N_NODES * DD];   // H1 -> H2
__device__ float g_bufB[N_NODES * DD];   // agg1 -> agg2
__device__ float g_C1[4 * DD];
__device__ float g_bc1[DD];
__device__ float g_C2[4 * DD];
__device__ float g_bc2[DD];
__device__ float g_bnsum1[DD];
__device__ float g_bnsq1[DD];
__device__ float g_bnsum2[DD];
__device__ float g_bnsq2[DD];
__device__ float g_sc[DD];
__device__ float g_sh[DD];
__device__ unsigned g_gmax[N_GRAPHS];
__device__ float g_denom[N_GRAPHS];
__device__ float g_gate[N_NODES];
// CSR (dst-sorted, with permuted src and edge_attr)
__device__ int    g_deg[N_NODES];
__device__ int    g_start[N_NODES];
__device__ int    g_cursor[N_NODES];
__device__ int    g_srcs[N_EDGES];
__device__ float4 g_eas[N_EDGES];
__device__ int    g_part[NSB];
__device__ int    g_part2[NSB];

// ---------------- helpers ---------------------------------------------------
__device__ __forceinline__ float leaky(float v) {
    return v >= 0.f ? v : NEG_SLOPE * v;
}
__device__ __forceinline__ unsigned enc_f(float x) {
    unsigned u = __float_as_uint(x);
    return (u & 0x80000000u) ? ~u : (u | 0x80000000u);
}
__device__ __forceinline__ float dec_f(unsigned u) {
    return (u & 0x80000000u) ? __uint_as_float(u ^ 0x80000000u) : __uint_as_float(~u);
}
__device__ __forceinline__ void red_add_v4(float* p, float a, float b, float c, float d) {
    asm volatile("red.global.add.v4.f32 [%0], {%1, %2, %3, %4};"
                 :: "l"(p), "f"(a), "f"(b), "f"(c), "f"(d) : "memory");
}
__device__ __forceinline__ ull dup2(float x) {
    ull r; unsigned u = __float_as_uint(x);
    asm("mov.b64 %0, {%1, %1};" : "=l"(r) : "r"(u));
    return r;
}
__device__ __forceinline__ void fma2(ull& d, ull a, ull b) {
    asm("fma.rn.f32x2 %0, %1, %2, %0;" : "+l"(d) : "l"(a), "l"(b));
}
__device__ __forceinline__ float2 up2(ull v) {
    float2 f; asm("mov.b64 {%0, %1}, %2;" : "=f"(f.x), "=f"(f.y) : "l"(v));
    return f;
}
__device__ __forceinline__ unsigned tf32c(float x) {
    unsigned r;
    asm("cvt.rna.tf32.f32 %0, %1;" : "=r"(r) : "f"(x));
    return r;
}
__device__ __forceinline__ void mma_tf32(float d[4], const unsigned a[4],
                                         unsigned b0, unsigned b1) {
    asm volatile(
        "mma.sync.aligned.m16n8k8.row.col.f32.tf32.tf32.f32 "
        "{%0,%1,%2,%3}, {%4,%5,%6,%7}, {%8,%9}, {%0,%1,%2,%3};"
        : "+f"(d[0]), "+f"(d[1]), "+f"(d[2]), "+f"(d[3])
        : "r"(a[0]), "r"(a[1]), "r"(a[2]), "r"(a[3]), "r"(b0), "r"(b1));
}

// ---------------- zero / init kernels ---------------------------------------
__global__ void zero_init(float* out, int out_n) {
    int i = blockIdx.x * blockDim.x + threadIdx.x;
    if (i < N_NODES) g_deg[i] = 0;
    if (i < DD) {
        g_bnsum1[i] = 0.f; g_bnsq1[i] = 0.f;
        g_bnsum2[i] = 0.f; g_bnsq2[i] = 0.f;
    }
    if (i < N_GRAPHS) { g_gmax[i] = 0u; g_denom[i] = 0.f; }
    for (int k = i; k < out_n; k += gridDim.x * blockDim.x) out[k] = 0.f;
}

// ---------------- CSR build --------------------------------------------------
__global__ void hist_kernel(const int* __restrict__ dst) {
    int e = blockIdx.x * blockDim.x + threadIdx.x;
    if (e < N_EDGES) atomicAdd(&g_deg[__ldg(dst + e)], 1);
}
__global__ void scan1_kernel() {
    __shared__ int sh[256];
    int i = blockIdx.x * 256 + threadIdx.x;
    int v = (i < N_NODES) ? g_deg[i] : 0;
    sh[threadIdx.x] = v; __syncthreads();
#pragma unroll
    for (int off = 1; off < 256; off <<= 1) {
        int tv = (threadIdx.x >= off) ? sh[threadIdx.x - off] : 0;
        __syncthreads();
        sh[threadIdx.x] += tv;
        __syncthreads();
    }
    if (i < N_NODES) g_start[i] = sh[threadIdx.x] - v;
    if (threadIdx.x == 255) g_part[blockIdx.x] = sh[255];
}
__global__ void scan2_kernel() {
    __shared__ int sh[256];
    int t = threadIdx.x;
    int v = (t < NSB) ? g_part[t] : 0;
    sh[t] = v; __syncthreads();
#pragma unroll
    for (int off = 1; off < 256; off <<= 1) {
        int tv = (t >= off) ? sh[t - off] : 0;
        __syncthreads();
        sh[t] += tv;
        __syncthreads();
    }
    if (t < NSB) g_part2[t] = sh[t] - v;
}
__global__ void scan3_kernel() {
    int i = blockIdx.x * 256 + threadIdx.x;
    if (i < N_NODES) {
        int s = g_start[i] + g_part2[blockIdx.x];
        g_start[i] = s;
        g_cursor[i] = s;
    }
}
__global__ void fill_kernel(const int* __restrict__ src,
                            const int* __restrict__ dst,
                            const float* __restrict__ ea) {
    int e = blockIdx.x * blockDim.x + threadIdx.x;
    if (e < N_EDGES) {
        int d = __ldg(dst + e);
        int p = atomicAdd(&g_cursor[d], 1);
        g_srcs[p] = __ldg(src + e);
        g_eas[p] = __ldg((const float4*)ea + e);
    }
}

// ---------------- combined edge matrices ------------------------------------
__global__ void combine_kernel(
    const float* __restrict__ l2w1, const float* __restrict__ l2b1,
    const float* __restrict__ lw1,  const float* __restrict__ lb1,
    const float* __restrict__ l2w2, const float* __restrict__ l2b2,
    const float* __restrict__ lw2,  const float* __restrict__ lb2)
{
    int d = threadIdx.x;   // 256 threads
    {
        float a0 = 0.f, a1 = 0.f, a2 = 0.f, a3 = 0.f, bb = 0.f;
        for (int f = 0; f < F_IN; f++) {
            float w = lw1[d * F_IN + f];
            float4 l2 = *(const float4*)(l2w1 + f * 4);
            a0 += l2.x * w; a1 += l2.y * w; a2 += l2.z * w; a3 += l2.w * w;
            bb += l2b1[f] * w;
        }
        g_C1[0 * DD + d] = a0; g_C1[1 * DD + d] = a1;
        g_C1[2 * DD + d] = a2; g_C1[3 * DD + d] = a3;
        g_bc1[d] = bb + lb1[d];
    }
    {
        float a0 = 0.f, a1 = 0.f, a2 = 0.f, a3 = 0.f, bb = 0.f;
        for (int f = 0; f < DD; f++) {
            float w = lw2[d * DD + f];
            float4 l2 = *(const float4*)(l2w2 + f * 4);
            a0 += l2.x * w; a1 += l2.y * w; a2 += l2.z * w; a3 += l2.w * w;
            bb += l2b2[f] * w;
        }
        g_C2[0 * DD + d] = a0; g_C2[1 * DD + d] = a1;
        g_C2[2 * DD + d] = a2; g_C2[3 * DD + d] = a3;
        g_bc2[d] = bb + lb2[d];
    }
}

// ---------------- GEMM (tf32 tensor cores, bias epilogue) --------------------
// out[m][n] = sum_k A'[m][k] * W[n][k] + bias[n];  A' = leaky(A*sc+sh) if sc.
__global__ void __launch_bounds__(256)
gemm_tf32(const float* __restrict__ A, const int* __restrict__ idx,
          const float* __restrict__ sc, const float* __restrict__ sh,
          const float* __restrict__ W, const float* __restrict__ bias,
          float* __restrict__ out, int M, int K)
{
    __shared__ unsigned As[128 * 36];
    __shared__ unsigned Bs[128 * 36];
    int t = threadIdx.x;
    int lane = t & 31;
    int wid = t >> 5;
    int wm = wid & 3, wn = wid >> 2;       // warp tile: rows wm*32, cols wn*64
    int bm = blockIdx.x * 128;
    int bn = blockIdx.y * 128;

    int lrow = t >> 1;
    int lkh = (t & 1) * 16;

    int m0 = bm + lrow;
    int mc = m0 < M ? m0 : (M - 1);
    int arow = idx ? __ldg(idx + mc) : mc;
    const float* Arow = A + (size_t)arow * K;
    const float* Wrow = W + (size_t)(bn + lrow) * K;

    float d[2][8][4];
#pragma unroll
    for (int i = 0; i < 2; i++)
#pragma unroll
        for (int j = 0; j < 8; j++)
#pragma unroll
            for (int c = 0; c < 4; c++) d[i][j][c] = 0.f;

    float4 va[4], vb[4];

    auto load_stage = [&](int kc) {
#pragma unroll
        for (int q = 0; q < 4; q++) {
            va[q] = __ldg((const float4*)(Arow + kc + lkh + q * 4));
            vb[q] = __ldg((const float4*)(Wrow + kc + lkh + q * 4));
        }
        if (sc) {
#pragma unroll
            for (int q = 0; q < 4; q++) {
                int ch = kc + lkh + q * 4;
                float4 s = __ldg((const float4*)(sc + ch));
                float4 h = __ldg((const float4*)(sh + ch));
                va[q].x = leaky(va[q].x * s.x + h.x);
                va[q].y = leaky(va[q].y * s.y + h.y);
                va[q].z = leaky(va[q].z * s.z + h.z);
                va[q].w = leaky(va[q].w * s.w + h.w);
            }
        }
    };
    auto store_stage = [&]() {
        unsigned* ap = As + lrow * 36 + lkh;
        unsigned* bp = Bs + lrow * 36 + lkh;
#pragma unroll
        for (int q = 0; q < 4; q++) {
            *(uint4*)(ap + q * 4) = make_uint4(tf32c(va[q].x), tf32c(va[q].y),
                                               tf32c(va[q].z), tf32c(va[q].w));
            *(uint4*)(bp + q * 4) = make_uint4(tf32c(vb[q].x), tf32c(vb[q].y),
                                               tf32c(vb[q].z), tf32c(vb[q].w));
        }
    };

    load_stage(0);
    store_stage();
    __syncthreads();

    for (int kc = 0; kc < K; kc += 32) {
        bool more = (kc + 32) < K;
        if (more) load_stage(kc + 32);
#pragma unroll
        for (int ks = 0; ks < 4; ks++) {
            int k0 = ks * 8;
            unsigned a[2][4];
            int ra = (wm * 32 + (lane >> 2)) * 36 + k0 + (lane & 3);
#pragma unroll
            for (int i = 0; i < 2; i++) {
                int base = ra + i * 16 * 36;
                a[i][0] = As[base];
                a[i][1] = As[base + 8 * 36];
                a[i][2] = As[base + 4];
                a[i][3] = As[base + 8 * 36 + 4];
            }
            int rb = (wn * 64 + (lane >> 2)) * 36 + k0 + (lane & 3);
#pragma unroll
            for (int j = 0; j < 8; j++) {
                unsigned b0 = Bs[rb + j * 8 * 36];
                unsigned b1 = Bs[rb + j * 8 * 36 + 4];
                mma_tf32(d[0][j], a[0], b0, b1);
                mma_tf32(d[1][j], a[1], b0, b1);
            }
        }
        if (more) {
            __syncthreads();
            store_stage();
            __syncthreads();
        }
    }

    // epilogue (+ bias)
    float2 bsv[8];
#pragma unroll
    for (int j = 0; j < 8; j++) {
        int col = bn + wn * 64 + j * 8 + (lane & 3) * 2;
        bsv[j] = __ldg((const float2*)(bias + col));
    }
#pragma unroll
    for (int i = 0; i < 2; i++) {
        int rg0 = bm + wm * 32 + i * 16 + (lane >> 2);
        int rg1 = rg0 + 8;
#pragma unroll
        for (int j = 0; j < 8; j++) {
            int col = bn + wn * 64 + j * 8 + (lane & 3) * 2;
            if (rg0 < M)
                *(float2*)(out + (size_t)rg0 * DD + col) =
                    make_float2(d[i][j][0] + bsv[j].x, d[i][j][1] + bsv[j].y);
            if (rg1 < M)
                *(float2*)(out + (size_t)rg1 * DD + col) =
                    make_float2(d[i][j][2] + bsv[j].x, d[i][j][3] + bsv[j].y);
        }
    }
}

// ---------------- per-edge packed accumulate (bias pre-folded into H) --------
__device__ __forceinline__ void edge_accum(
    ull acc[4], float4 at, ulonglong2 p, ulonglong2 q,
    const ull c0p[4], const ull c1p[4], const ull c2p[4], const ull c3p[4])
{
    const ull ABS2 = 0x7fffffff7fffffffull;
    const ull D505 = 0x3f0147ae3f0147aeull;  // dup2(0.505f)
    const ull D495 = 0x3efd70a43efd70a4ull;  // dup2(0.495f)
    ull ax = dup2(at.x), ay = dup2(at.y), az = dup2(at.z), aw = dup2(at.w);
    ull hh[4] = {p.x, p.y, q.x, q.y};
#pragma unroll
    for (int i = 0; i < 4; i++) {
        ull m = hh[i];
        fma2(m, ax, c0p[i]); fma2(m, ay, c1p[i]);
        fma2(m, az, c2p[i]); fma2(m, aw, c3p[i]);
        ull ab = m & ABS2;
        fma2(acc[i], D505, m);
        fma2(acc[i], D495, ab);
    }
}

// ---------------- CSR gather (permuted edges, packed f32x2, unroll-4) --------
__global__ void gather_kernel(const float* __restrict__ H,
                              const float* __restrict__ C,
                              float* __restrict__ agg,
                              float* __restrict__ bnsum,
                              float* __restrict__ bnsq)
{
    __shared__ float ssum[DD];
    __shared__ float ssq[DD];
    int t = threadIdx.x;
    ssum[t] = 0.f; ssq[t] = 0.f;
    __syncthreads();

    int lane = t & 31;
    int wid = (blockIdx.x * blockDim.x + t) >> 5;
    int nw = (gridDim.x * blockDim.x) >> 5;
    int d0 = lane * 8;

    ull c0p[4], c1p[4], c2p[4], c3p[4];
    {
        ulonglong2 u;
        u = *(const ulonglong2*)(C + 0 * DD + d0);     c0p[0] = u.x; c0p[1] = u.y;
        u = *(const ulonglong2*)(C + 0 * DD + d0 + 4); c0p[2] = u.x; c0p[3] = u.y;
        u = *(const ulonglong2*)(C + 1 * DD + d0);     c1p[0] = u.x; c1p[1] = u.y;
        u = *(const ulonglong2*)(C + 1 * DD + d0 + 4); c1p[2] = u.x; c1p[3] = u.y;
        u = *(const ulonglong2*)(C + 2 * DD + d0);     c2p[0] = u.x; c2p[1] = u.y;
        u = *(const ulonglong2*)(C + 2 * DD + d0 + 4); c2p[2] = u.x; c2p[3] = u.y;
        u = *(const ulonglong2*)(C + 3 * DD + d0);     c3p[0] = u.x; c3p[1] = u.y;
        u = *(const ulonglong2*)(C + 3 * DD + d0 + 4); c3p[2] = u.x; c3p[3] = u.y;
    }

    float sA[8], qA[8];
#pragma unroll
    for (int i = 0; i < 8; i++) { sA[i] = 0.f; qA[i] = 0.f; }

    for (int n = wid; n < N_NODES; n += nw) {
        int s0 = __ldg(g_start + n);
        int dg = __ldg(g_deg + n);
        ull acc[4] = {0ull, 0ull, 0ull, 0ull};

        int j = 0;
        for (; j + 3 < dg; j += 4) {
            int sa = __ldg(g_srcs + s0 + j);
            int sb = __ldg(g_srcs + s0 + j + 1);
            int sc2 = __ldg(g_srcs + s0 + j + 2);
            int sd = __ldg(g_srcs + s0 + j + 3);
            const ulonglong2* ha = (const ulonglong2*)(H + (size_t)sa * DD + d0);
            const ulonglong2* hb = (const ulonglong2*)(H + (size_t)sb * DD + d0);
            const ulonglong2* hc = (const ulonglong2*)(H + (size_t)sc2 * DD + d0);
            const ulonglong2* hd = (const ulonglong2*)(H + (size_t)sd * DD + d0);
            ulonglong2 pa = ha[0], qa = ha[1];
            ulonglong2 pb = hb[0], qb = hb[1];
            ulonglong2 pc = hc[0], qc = hc[1];
            ulonglong2 pd = hd[0], qd = hd[1];
            float4 at0 = __ldg((const float4*)g_eas + s0 + j);
            float4 at1 = __ldg((const float4*)g_eas + s0 + j + 1);
            float4 at2 = __ldg((const float4*)g_eas + s0 + j + 2);
            float4 at3 = __ldg((const float4*)g_eas + s0 + j + 3);
            edge_accum(acc, at0, pa, qa, c0p, c1p, c2p, c3p);
            edge_accum(acc, at1, pb, qb, c0p, c1p, c2p, c3p);
            edge_accum(acc, at2, pc, qc, c0p, c1p, c2p, c3p);
            edge_accum(acc, at3, pd, qd, c0p, c1p, c2p, c3p);
        }
        for (; j < dg; j++) {
            int sa = __ldg(g_srcs + s0 + j);
            float4 at0 = __ldg((const float4*)g_eas + s0 + j);
            const ulonglong2* ha = (const ulonglong2*)(H + (size_t)sa * DD + d0);
            ulonglong2 pa = ha[0], qa = ha[1];
            edge_accum(acc, at0, pa, qa, c0p, c1p, c2p, c3p);
        }

        ulonglong2* op = (ulonglong2*)(agg + (size_t)n * DD + d0);
        op[0] = make_ulonglong2(acc[0], acc[1]);
        op[1] = make_ulonglong2(acc[2], acc[3]);

#pragma unroll
        for (int i = 0; i < 4; i++) {
            float2 f = up2(acc[i]);
            sA[2 * i]     += f.x;  qA[2 * i]     += f.x * f.x;
            sA[2 * i + 1] += f.y;  qA[2 * i + 1] += f.y * f.y;
        }
    }
#pragma unroll
    for (int i = 0; i < 8; i++) {
        atomicAdd(&ssum[d0 + i], sA[i]);
        atomicAdd(&ssq[d0 + i], qA[i]);
    }
    __syncthreads();
    atomicAdd(&bnsum[t], ssum[t]);
    atomicAdd(&bnsq[t], ssq[t]);
}

// ---------------- BN scale/shift from stats ----------------------------------
__global__ void bnsc_kernel(const float* __restrict__ w, const float* __restrict__ b,
                            const float* __restrict__ bnsum, const float* __restrict__ bnsq)
{
    int c = threadIdx.x;
    const float invN = 1.f / (float)N_NODES;
    float m = bnsum[c] * invN;
    float var = bnsq[c] * invN - m * m;
    float s = w[c] * rsqrtf(var + EPS);
    g_sc[c] = s;
    g_sh[c] = b[c] - m * s;
}

// ---------------- gate (read-only) + segment max ------------------------------
__global__ void gate_kernel(const float* __restrict__ X,
                            const float* __restrict__ gw,
                            const float* __restrict__ gb,
                            const int* __restrict__ batch)
{
    int wid = (blockIdx.x * blockDim.x + threadIdx.x) >> 5;
    int lane = threadIdx.x & 31;
    if (wid >= N_NODES) return;
    int d0 = lane * 8;
    const float4* xp = (const float4*)(X + (size_t)wid * DD + d0);
    float4 h0 = __ldg(xp), h1 = __ldg(xp + 1);
    float v[8] = {h0.x, h0.y, h0.z, h0.w, h1.x, h1.y, h1.z, h1.w};
    float gsum = 0.f;
#pragma unroll
    for (int i = 0; i < 8; i++) {
        int ch = d0 + i;
        gsum += leaky(v[i] * g_sc[ch] + g_sh[ch]) * __ldg(gw + ch);
    }
#pragma unroll
    for (int off = 16; off; off >>= 1) gsum += __shfl_xor_sync(0xffffffffu, gsum, off);
    if (lane == 0) {
        gsum += __ldg(gb);
        g_gate[wid] = gsum;
        atomicMax(&g_gmax[__ldg(batch + wid)], enc_f(gsum));
    }
}

// ---------------- fused exp + denom + unnormalized weighted aggregation ------
__global__ void wfinal_kernel(const float* __restrict__ X,
                              const int* __restrict__ batch,
                              float* __restrict__ out)
{
    int wid = (blockIdx.x * blockDim.x + threadIdx.x) >> 5;
    int lane = threadIdx.x & 31;
    if (wid >= N_NODES) return;
    int b = __ldg(batch + wid);
    float e = __expf(g_gate[wid] - dec_f(g_gmax[b]));
    if (lane == 0) atomicAdd(&g_denom[b], e);
    int d0 = lane * 8;
    const float4* xp = (const float4*)(X + (size_t)wid * DD + d0);
    float4 h0 = __ldg(xp), h1 = __ldg(xp + 1);
    float v[8] = {h0.x, h0.y, h0.z, h0.w, h1.x, h1.y, h1.z, h1.w};
#pragma unroll
    for (int i = 0; i < 8; i++) {
        int ch = d0 + i;
        v[i] = e * leaky(v[i] * g_sc[ch] + g_sh[ch]);
    }
    float* op = out + (size_t)b * DD + d0;
    red_add_v4(op,     v[0], v[1], v[2], v[3]);
    red_add_v4(op + 4, v[4], v[5], v[6], v[7]);
}

// ---------------- normalize out by denom --------------------------------------
__global__ void norm_kernel(float* __restrict__ out)
{
    int i = blockIdx.x * blockDim.x + threadIdx.x;
    if (i >= N_GRAPHS * DD) return;
    float dn = g_denom[i >> 8];
    out[i] = dn > 0.f ? out[i] / dn : 0.f;
}

// ---------------- launch -----------------------------------------------------
extern "C" void kernel_launch(void* const* d_in, const int* in_sizes, int n_in,
                              void* d_out, int out_size)
{
    const int*   node_ids  = (const int*)d_in[0];
    const int*   edge_index= (const int*)d_in[1];
    const float* edge_attr = (const float*)d_in[2];
    const int*   batch     = (const int*)d_in[3];
    const float* emb       = (const float*)d_in[4];
    const float* c1_lin2_w = (const float*)d_in[5];
    const float* c1_lin2_b = (const float*)d_in[6];
    const float* c1_lin_w  = (const float*)d_in[7];
    const float* c1_lin_b  = (const float*)d_in[8];
    const float* bn1_w     = (const float*)d_in[9];
    const float* bn1_b     = (const float*)d_in[10];
    const float* c2_lin2_w = (const float*)d_in[11];
    const float* c2_lin2_b = (const float*)d_in[12];
    const float* c2_lin_w  = (const float*)d_in[13];
    const float* c2_lin_b  = (const float*)d_in[14];
    const float* bn2_w     = (const float*)d_in[15];
    const float* bn2_b     = (const float*)d_in[16];
    const float* gate_w    = (const float*)d_in[17];
    const float* gate_b    = (const float*)d_in[18];
    float* out = (float*)d_out;

    const int* src = edge_index;
    const int* dst = edge_index + N_EDGES;

    float *pA, *pB, *pC1, *pbc1, *pC2, *pbc2, *psc, *psh;
    float *pbs1, *pbq1, *pbs2, *pbq2;
    cudaGetSymbolAddress((void**)&pA,   g_bufA);
    cudaGetSymbolAddress((void**)&pB,   g_bufB);
    cudaGetSymbolAddress((void**)&pC1,  g_C1);
    cudaGetSymbolAddress((void**)&pbc1, g_bc1);
    cudaGetSymbolAddress((void**)&pC2,  g_C2);
    cudaGetSymbolAddress((void**)&pbc2, g_bc2);
    cudaGetSymbolAddress((void**)&psc,  g_sc);
    cudaGetSymbolAddress((void**)&psh,  g_sh);
    cudaGetSymbolAddress((void**)&pbs1, g_bnsum1);
    cudaGetSymbolAddress((void**)&pbq1, g_bnsq1);
    cudaGetSymbolAddress((void**)&pbs2, g_bnsum2);
    cudaGetSymbolAddress((void**)&pbq2, g_bnsq2);

    // ---- init (deg, bn stats, graph accum, out) ----
    zero_init<<<NSB, 256>>>(out, out_size);

    // ---- CSR build (dst-sorted, permuted src + edge_attr) ----
    hist_kernel<<<(N_EDGES + 255) / 256, 256>>>(dst);
    scan1_kernel<<<NSB, 256>>>();
    scan2_kernel<<<1, 256>>>();
    scan3_kernel<<<NSB, 256>>>();
    fill_kernel<<<(N_EDGES + 255) / 256, 256>>>(src, dst, edge_attr);

    // ---- combined edge matrices ----
    combine_kernel<<<1, 256>>>(c1_lin2_w, c1_lin2_b, c1_lin_w, c1_lin_b,
                               c2_lin2_w, c2_lin2_b, c2_lin_w, c2_lin_b);

    dim3 gg((N_NODES + 127) / 128, DD / 128);

    // ---- layer 1: H1 = emb[node_ids] @ W1^T + bc1 (tf32 tensor cores) ----
    gemm_tf32<<<gg, 256>>>(emb, node_ids, nullptr, nullptr, c1_lin_w, pbc1, pA, N_NODES, F_IN);

    // ---- conv1 gather -> agg1 (bufB) + bn1 stats ----
    gather_kernel<<<1024, 256>>>(pA, pC1, pB, pbs1, pbq1);
    bnsc_kernel<<<1, 256>>>(bn1_w, bn1_b, pbs1, pbq1);

    // ---- layer 2: H2 = leaky(bn1(agg1)) @ W2^T + bc2 (BN fused into A-load) ----
    gemm_tf32<<<gg, 256>>>(pB, nullptr, psc, psh, c2_lin_w, pbc2, pA, N_NODES, DD);

    // ---- conv2 gather -> agg2 (bufB) + bn2 stats ----
    gather_kernel<<<1024, 256>>>(pA, pC2, pB, pbs2, pbq2);
    bnsc_kernel<<<1, 256>>>(bn2_w, bn2_b, pbs2, pbq2);

    // ---- gate (read-only) + segment max ----
    int nb = (N_NODES * 32 + 255) / 256;
    gate_kernel<<<nb, 256>>>(pB, gate_w, gate_b, batch);

    // ---- fused softmax + weighted aggregation (unnormalized), then normalize ----
    wfinal_kernel<<<nb, 256>>>(pB, batch, out);
    norm_kernel<<<(N_GRAPHS * DD + 255) / 256, 256>>>(out);
}